// round 4
// baseline (speedup 1.0000x reference)
#include <cuda_runtime.h>
#include <math.h>
#include <stdint.h>

// Problem dims
#define LL  4
#define BB  2
#define SSq 512
#define MMm 512
#define DDd 1024
#define HHh 16
#define DKk 64
#define FFf 4096
#define TTt (SSq + MMm)   // 1024

// ---------------- scratch ----------------
__device__ float g_pos[TTt * DDd];
__device__ float g_kv [BB * TTt * DDd];
__device__ float g_q  [BB * SSq * DDd];
__device__ float g_k  [BB * TTt * DDd];
__device__ float g_v  [BB * TTt * DDd];
__device__ float g_r  [TTt * DDd];
__device__ float g_attn[BB * SSq * DDd];
__device__ float g_tmp [BB * SSq * DDd];
__device__ float g_ff  [BB * SSq * FFf];
__device__ float g_h   [BB * SSq * DDd];
__device__ float g_h1  [BB * SSq * DDd];

// ---------------- PTX helpers ----------------
__device__ __forceinline__ uint32_t f2tf32(float f) {
    uint32_t u;
    asm("cvt.rna.tf32.f32 %0, %1;" : "=r"(u) : "f"(f));
    return u;
}
__device__ __forceinline__ void mma_tf32(float c[4], const uint32_t a[4], const uint32_t b[2]) {
    asm volatile(
        "mma.sync.aligned.m16n8k8.row.col.f32.tf32.tf32.f32 "
        "{%0,%1,%2,%3},{%4,%5,%6,%7},{%8,%9},{%0,%1,%2,%3};"
        : "+f"(c[0]), "+f"(c[1]), "+f"(c[2]), "+f"(c[3])
        : "r"(a[0]), "r"(a[1]), "r"(a[2]), "r"(a[3]), "r"(b[0]), "r"(b[1]));
}

// ---------------- positional encodings ----------------
__global__ void pos_kernel(float* __restrict__ pos)
{
    int idx = blockIdx.x * blockDim.x + threadIdx.x;
    if (idx >= TTt * DDd) return;
    int t = idx / DDd, d = idx % DDd;
    int j = (d < DDd / 2) ? d : d - DDd / 2;
    double invf = exp(((double)(-2 * j) / (double)DDd) * 9.210340371976184);
    double ang  = (double)(TTt - 1 - t) * invf;
    double kk   = floor(ang * 0.15915494309189535);
    float a = (float)(ang - kk * 6.283185307179586);
    pos[idx] = (d < DDd / 2) ? sinf(a) : cosf(a);
}

// ---------------- concat(memory[l], h) -> kv ----------------
__global__ void concat_kernel(float* __restrict__ kv, const float* __restrict__ mem,
                              const float* __restrict__ h)
{
    int idx = blockIdx.x * blockDim.x + threadIdx.x;
    if (idx >= BB * TTt * DDd) return;
    int d = idx % DDd;
    int t = (idx / DDd) % TTt;
    int b = idx / (DDd * TTt);
    kv[idx] = (t < MMm) ? mem[((size_t)b * MMm + t) * DDd + d]
                        : h[((size_t)b * SSq + (t - MMm)) * DDd + d];
}

// ======================================================================
// GEMM core: C = alpha*A@B (+bias)(+relu). BM x (NWN*32) tile, BK=16,
// 256 threads. tf32 converted once at smem store.
// ======================================================================
template<int BM, int NWN>
__device__ __forceinline__ void gemm_core(
    const float* __restrict__ A, const float* __restrict__ B, float* __restrict__ C,
    int N, int K, float alpha, const float* __restrict__ bias, int relu,
    int bx, int by)
{
    constexpr int BN = NWN * 32;
    constexpr int NWM = 8 / NWN;
    constexpr int WM = BM / NWM;
    constexpr int MT = WM / 16;
    constexpr int BPITCH = BN + 8;
    constexpr int NA_CH = BM / 64;
    constexpr int NB_CH = BN / 64;

    __shared__ uint32_t As[2][BM][20];
    __shared__ uint32_t Bs[2][16][BPITCH];

    int tid = threadIdx.x, lane = tid & 31, warp = tid >> 5;
    int g = lane >> 2, tg = lane & 3;
    int warp_m = warp % NWM, warp_n = warp / NWM;
    int wm = warp_m * WM, wn = warp_n * 32;

    const float* Ag = A + (size_t)by * BM * K;
    const float* Bg = B + (size_t)bx * BN;

    float acc[MT][4][4];
#pragma unroll
    for (int mt = 0; mt < MT; mt++)
#pragma unroll
        for (int nt = 0; nt < 4; nt++)
#pragma unroll
            for (int i = 0; i < 4; i++) acc[mt][nt][i] = 0.f;

    int ar[NA_CH], ak[NA_CH];
#pragma unroll
    for (int j = 0; j < NA_CH; j++) {
        int c = tid + j * 256;
        ar[j] = c >> 2; ak[j] = (c & 3) * 4;
    }
    int bk[NB_CH], bn[NB_CH];
#pragma unroll
    for (int j = 0; j < NB_CH; j++) {
        int c = tid + j * 256;
        if (BN == 128) { bk[j] = c >> 5; bn[j] = (c & 31) * 4; }
        else           { bk[j] = c >> 4; bn[j] = (c & 15) * 4; }
    }

    int nk = K / 16;
    float4 sA[NA_CH], sB[NB_CH];

#pragma unroll
    for (int j = 0; j < NA_CH; j++)
        sA[j] = *(const float4*)(Ag + (size_t)ar[j] * K + ak[j]);
#pragma unroll
    for (int j = 0; j < NB_CH; j++)
        sB[j] = *(const float4*)(Bg + (size_t)bk[j] * N + bn[j]);
#pragma unroll
    for (int j = 0; j < NA_CH; j++) {
        uint4 u = make_uint4(f2tf32(sA[j].x), f2tf32(sA[j].y), f2tf32(sA[j].z), f2tf32(sA[j].w));
        *(uint4*)&As[0][ar[j]][ak[j]] = u;
    }
#pragma unroll
    for (int j = 0; j < NB_CH; j++) {
        uint4 u = make_uint4(f2tf32(sB[j].x), f2tf32(sB[j].y), f2tf32(sB[j].z), f2tf32(sB[j].w));
        *(uint4*)&Bs[0][bk[j]][bn[j]] = u;
    }
    __syncthreads();

    for (int kt = 0; kt < nk; kt++) {
        int buf = kt & 1;
        bool more = (kt + 1 < nk);
        if (more) {
#pragma unroll
            for (int j = 0; j < NA_CH; j++)
                sA[j] = *(const float4*)(Ag + (size_t)ar[j] * K + (kt + 1) * 16 + ak[j]);
#pragma unroll
            for (int j = 0; j < NB_CH; j++)
                sB[j] = *(const float4*)(Bg + (size_t)((kt + 1) * 16 + bk[j]) * N + bn[j]);
        }

#pragma unroll
        for (int ks = 0; ks < 2; ks++) {
            uint32_t af[MT][4], bf[4][2];
#pragma unroll
            for (int mt = 0; mt < MT; mt++) {
                int row = wm + mt * 16;
                af[mt][0] = As[buf][row + g][ks * 8 + tg];
                af[mt][1] = As[buf][row + g + 8][ks * 8 + tg];
                af[mt][2] = As[buf][row + g][ks * 8 + tg + 4];
                af[mt][3] = As[buf][row + g + 8][ks * 8 + tg + 4];
            }
#pragma unroll
            for (int nt = 0; nt < 4; nt++) {
                int col = wn + nt * 8 + g;
                bf[nt][0] = Bs[buf][ks * 8 + tg][col];
                bf[nt][1] = Bs[buf][ks * 8 + tg + 4][col];
            }
#pragma unroll
            for (int mt = 0; mt < MT; mt++)
#pragma unroll
                for (int nt = 0; nt < 4; nt++) mma_tf32(acc[mt][nt], af[mt], bf[nt]);
        }

        if (more) {
            int nb = buf ^ 1;
#pragma unroll
            for (int j = 0; j < NA_CH; j++) {
                uint4 u = make_uint4(f2tf32(sA[j].x), f2tf32(sA[j].y), f2tf32(sA[j].z), f2tf32(sA[j].w));
                *(uint4*)&As[nb][ar[j]][ak[j]] = u;
            }
#pragma unroll
            for (int j = 0; j < NB_CH; j++) {
                uint4 u = make_uint4(f2tf32(sB[j].x), f2tf32(sB[j].y), f2tf32(sB[j].z), f2tf32(sB[j].w));
                *(uint4*)&Bs[nb][bk[j]][bn[j]] = u;
            }
            __syncthreads();
        }
    }

#pragma unroll
    for (int mt = 0; mt < MT; mt++) {
#pragma unroll
        for (int nt = 0; nt < 4; nt++) {
            int row = by * BM + wm + mt * 16 + g;
            int col = bx * BN + wn + nt * 8 + tg * 2;
            float bx0 = 0.f, bx1 = 0.f;
            if (bias) { bx0 = bias[col]; bx1 = bias[col + 1]; }
            float v0 = acc[mt][nt][0] * alpha + bx0;
            float v1 = acc[mt][nt][1] * alpha + bx1;
            float v2 = acc[mt][nt][2] * alpha + bx0;
            float v3 = acc[mt][nt][3] * alpha + bx1;
            if (relu) {
                v0 = fmaxf(v0, 0.f); v1 = fmaxf(v1, 0.f);
                v2 = fmaxf(v2, 0.f); v3 = fmaxf(v3, 0.f);
            }
            *(float2*)(C + (size_t)row * N + col)       = make_float2(v0, v1);
            *(float2*)(C + (size_t)(row + 8) * N + col) = make_float2(v2, v3);
        }
    }
}

template<int BM, int NWN>
__global__ void __launch_bounds__(256) tc_gemm_k(
    const float* __restrict__ A, const float* __restrict__ B, float* __restrict__ C,
    int N, int K, float alpha, const float* __restrict__ bias, int relu)
{
    gemm_core<BM, NWN>(A, B, C, N, K, alpha, bias, relu, blockIdx.x, blockIdx.y);
}

// grouped q/k/v/r projections: z selects the gemm (BM=128, BN=64)
__global__ void __launch_bounds__(256) grouped_qkvr(
    const float* __restrict__ hc, const float* __restrict__ kv, const float* __restrict__ pos,
    const float* __restrict__ Wq, const float* __restrict__ Wk,
    const float* __restrict__ Wv, const float* __restrict__ Wr,
    float* __restrict__ q, float* __restrict__ k, float* __restrict__ v, float* __restrict__ r)
{
    int z = blockIdx.z;
    const float* A; const float* B; float* C; int mb; float alpha = 1.f;
    if (z == 0)      { A = hc;  B = Wq; C = q; mb = (BB * SSq) / 128; alpha = 0.125f; }
    else if (z == 1) { A = kv;  B = Wk; C = k; mb = (BB * TTt) / 128; }
    else if (z == 2) { A = kv;  B = Wv; C = v; mb = (BB * TTt) / 128; }
    else             { A = pos; B = Wr; C = r; mb = TTt / 128; }
    if ((int)blockIdx.y >= mb) return;
    gemm_core<128, 2>(A, B, C, DDd, DDd, alpha, nullptr, 0, blockIdx.x, blockIdx.y);
}

// ======================================================================
// Flash fused attention: content + rel(window) + mask + ONLINE softmax + P@V
// CTA = 32 query rows of one (b,h). 256 threads, 8 warps. ~84KB smem.
// ======================================================================
#define SMT   32
#define TN    64
#define QPITCH 68
#define WPITCH 100
// floats: Qc+Qr 2*32*68, KV 64*68, Rw 96*68, QRW 32*100, Pt 32*68,
//         partm 128, parts 128, rowm 32, rowsum 32
#define SMEM_ATTN_FLOATS (2*SMT*QPITCH + 64*QPITCH + 96*QPITCH + SMT*WPITCH + SMT*QPITCH + 128 + 128 + 32 + 32)
#define SMEM_ATTN_BYTES  (SMEM_ATTN_FLOATS * 4)

__global__ void __launch_bounds__(256) fused_attn(
    const float* __restrict__ q, const float* __restrict__ k, const float* __restrict__ v,
    const float* __restrict__ r, const float* __restrict__ rwb, const float* __restrict__ rrb,
    float* __restrict__ attn)
{
    extern __shared__ float sm[];
    uint32_t* Qcb  = (uint32_t*)sm;                       // [32][68] tf32
    uint32_t* Qrb  = Qcb + SMT * QPITCH;                  // [32][68]
    uint32_t* Ktb  = Qrb + SMT * QPITCH;                  // [64][68]  K then V
    uint32_t* Rwb  = Ktb + 64 * QPITCH;                   // [96][68]
    float* QRW     = (float*)(Rwb + 96 * QPITCH);         // [32][100]
    uint32_t* Pt   = (uint32_t*)(QRW + SMT * WPITCH);     // [32][68]
    float* partm   = (float*)(Pt + SMT * QPITCH);         // [32][4]
    float* parts   = partm + 128;                          // [32][4]
    float* rowm    = parts + 128;                          // [32]
    float* rowsum  = rowm + 32;                            // [32]

    int tid = threadIdx.x, lane = tid & 31, warp = tid >> 5;
    int g = lane >> 2, tg = lane & 3;
    int s0 = blockIdx.x * SMT;
    int b = blockIdx.y >> 4, h = blockIdx.y & 15;

    const float* qb = q + (size_t)b * SSq * DDd + h * DKk;
    const float* kb = k + (size_t)b * TTt * DDd + h * DKk;
    const float* vb = v + (size_t)b * TTt * DDd + h * DKk;
    const float* rb = r + h * DKk;
    const float* wbv = rwb + h * DKk;
    const float* rbv = rrb + h * DKk;

    // phase 1: Qc = q + rwb, Qr = q + rrb (tf32); init row stats
#pragma unroll
    for (int j = 0; j < 2; j++) {
        int c = tid + j * 256;
        int row = c >> 4, k0 = (c & 15) * 4;
        float4 qv = *(const float4*)(qb + (size_t)(s0 + row) * DDd + k0);
        float4 w4 = *(const float4*)(wbv + k0);
        float4 r4 = *(const float4*)(rbv + k0);
        Qcb[row * QPITCH + k0 + 0] = f2tf32(qv.x + w4.x);
        Qcb[row * QPITCH + k0 + 1] = f2tf32(qv.y + w4.y);
        Qcb[row * QPITCH + k0 + 2] = f2tf32(qv.z + w4.z);
        Qcb[row * QPITCH + k0 + 3] = f2tf32(qv.w + w4.w);
        Qrb[row * QPITCH + k0 + 0] = f2tf32(qv.x + r4.x);
        Qrb[row * QPITCH + k0 + 1] = f2tf32(qv.y + r4.y);
        Qrb[row * QPITCH + k0 + 2] = f2tf32(qv.z + r4.z);
        Qrb[row * QPITCH + k0 + 3] = f2tf32(qv.w + r4.w);
    }
    if (tid < 32) { rowm[tid] = -1e30f; rowsum[tid] = 0.f; }

    int ntiles = (s0 + 543) / 64 + 1;
    int wm2 = (warp & 1) * 16;
    int wn2 = (warp >> 1) * 16;
    int wn3 = (warp >> 1) * 24;
    int wi  = warp >> 1;
    int r1 = wm2 + g, r2 = r1 + 8;

    float oacc[2][4];
#pragma unroll
    for (int nt = 0; nt < 2; nt++)
#pragma unroll
        for (int i = 0; i < 4; i++) oacc[nt][i] = 0.f;

    for (int it = 0; it < ntiles; it++) {
        int t0 = it * TN;
        int jb = t0 - s0 + 480;
        __syncthreads();   // smem buffers safe to overwrite (covers phase-1 too)

        // load K tile [64][64]
#pragma unroll
        for (int j = 0; j < 4; j++) {
            int c = tid + j * 256;
            int row = c >> 4, k0 = (c & 15) * 4;
            float4 kv4 = *(const float4*)(kb + (size_t)(t0 + row) * DDd + k0);
            Ktb[row * QPITCH + k0 + 0] = f2tf32(kv4.x);
            Ktb[row * QPITCH + k0 + 1] = f2tf32(kv4.y);
            Ktb[row * QPITCH + k0 + 2] = f2tf32(kv4.z);
            Ktb[row * QPITCH + k0 + 3] = f2tf32(kv4.w);
        }
        // load R window [96][64]
#pragma unroll
        for (int j = 0; j < 6; j++) {
            int c = tid + j * 256;
            int row = c >> 4, k0 = (c & 15) * 4;
            int jg = jb + row; if (jg > TTt - 1) jg = TTt - 1;
            float4 rv4 = *(const float4*)(rb + (size_t)jg * DDd + k0);
            Rwb[row * QPITCH + k0 + 0] = f2tf32(rv4.x);
            Rwb[row * QPITCH + k0 + 1] = f2tf32(rv4.y);
            Rwb[row * QPITCH + k0 + 2] = f2tf32(rv4.z);
            Rwb[row * QPITCH + k0 + 3] = f2tf32(rv4.w);
        }
        __syncthreads();   // sync1: tiles ready

        // QK content + rel MMAs
        float ca[2][4], ra[3][4];
#pragma unroll
        for (int nt = 0; nt < 2; nt++)
#pragma unroll
            for (int i = 0; i < 4; i++) ca[nt][i] = 0.f;
#pragma unroll
        for (int nt = 0; nt < 3; nt++)
#pragma unroll
            for (int i = 0; i < 4; i++) ra[nt][i] = 0.f;

#pragma unroll
        for (int k8 = 0; k8 < 64; k8 += 8) {
            uint32_t af[4], afr[4];
            af[0]  = Qcb[(wm2 + g) * QPITCH + k8 + tg];
            af[1]  = Qcb[(wm2 + g + 8) * QPITCH + k8 + tg];
            af[2]  = Qcb[(wm2 + g) * QPITCH + k8 + tg + 4];
            af[3]  = Qcb[(wm2 + g + 8) * QPITCH + k8 + tg + 4];
            afr[0] = Qrb[(wm2 + g) * QPITCH + k8 + tg];
            afr[1] = Qrb[(wm2 + g + 8) * QPITCH + k8 + tg];
            afr[2] = Qrb[(wm2 + g) * QPITCH + k8 + tg + 4];
            afr[3] = Qrb[(wm2 + g + 8) * QPITCH + k8 + tg + 4];
#pragma unroll
            for (int nt = 0; nt < 2; nt++) {
                uint32_t bf[2];
                int col = wn2 + nt * 8 + g;
                bf[0] = Ktb[col * QPITCH + k8 + tg];
                bf[1] = Ktb[col * QPITCH + k8 + tg + 4];
                mma_tf32(ca[nt], af, bf);
            }
#pragma unroll
            for (int nt = 0; nt < 3; nt++) {
                uint32_t bf[2];
                int col = wn3 + nt * 8 + g;
                bf[0] = Rwb[col * QPITCH + k8 + tg];
                bf[1] = Rwb[col * QPITCH + k8 + tg + 4];
                mma_tf32(ra[nt], afr, bf);
            }
        }
        // write rel window
#pragma unroll
        for (int nt = 0; nt < 3; nt++) {
            int c0 = wn3 + nt * 8 + tg * 2;
            QRW[r1 * WPITCH + c0]     = ra[nt][0];
            QRW[r1 * WPITCH + c0 + 1] = ra[nt][1];
            QRW[r2 * WPITCH + c0]     = ra[nt][2];
            QRW[r2 * WPITCH + c0 + 1] = ra[nt][3];
        }
        __syncthreads();   // sync2: QRW ready, K reads done

        // combine -> logits in regs
        float l[2][4];
#pragma unroll
        for (int nt = 0; nt < 2; nt++) {
            int tts = wn2 + nt * 8 + tg * 2;
#pragma unroll
            for (int i = 0; i < 4; i++) {
                int si = wm2 + g + ((i >= 2) ? 8 : 0);
                int tt = tts + (i & 1);
                int t = t0 + tt, s = s0 + si;
                l[nt][i] = (t - s <= MMm)
                    ? ca[nt][i] + QRW[si * WPITCH + tt + (SMT - 1) - si]
                    : -1e30f;
            }
        }
        // tile row max (partial within warp cols)
        float mx1 = fmaxf(fmaxf(l[0][0], l[0][1]), fmaxf(l[1][0], l[1][1]));
        float mx2 = fmaxf(fmaxf(l[0][2], l[0][3]), fmaxf(l[1][2], l[1][3]));
        mx1 = fmaxf(mx1, __shfl_xor_sync(0xffffffffu, mx1, 1));
        mx1 = fmaxf(mx1, __shfl_xor_sync(0xffffffffu, mx1, 2));
        mx2 = fmaxf(mx2, __shfl_xor_sync(0xffffffffu, mx2, 1));
        mx2 = fmaxf(mx2, __shfl_xor_sync(0xffffffffu, mx2, 2));
        if (tg == 0) { partm[r1 * 4 + wi] = mx1; partm[r2 * 4 + wi] = mx2; }

        // load V into the K buffer (K reads finished before sync2)
#pragma unroll
        for (int j = 0; j < 4; j++) {
            int c = tid + j * 256;
            int row = c >> 4, k0 = (c & 15) * 4;
            float4 vv4 = *(const float4*)(vb + (size_t)(t0 + row) * DDd + k0);
            Ktb[row * QPITCH + k0 + 0] = f2tf32(vv4.x);
            Ktb[row * QPITCH + k0 + 1] = f2tf32(vv4.y);
            Ktb[row * QPITCH + k0 + 2] = f2tf32(vv4.z);
            Ktb[row * QPITCH + k0 + 3] = f2tf32(vv4.w);
        }
        __syncthreads();   // sync3: partmax + V ready

        // finalize max, exp, partial sums, write P, rescale O
        float tm1 = fmaxf(fmaxf(partm[r1 * 4 + 0], partm[r1 * 4 + 1]),
                          fmaxf(partm[r1 * 4 + 2], partm[r1 * 4 + 3]));
        float tm2 = fmaxf(fmaxf(partm[r2 * 4 + 0], partm[r2 * 4 + 1]),
                          fmaxf(partm[r2 * 4 + 2], partm[r2 * 4 + 3]));
        float m1 = fmaxf(rowm[r1], tm1);
        float m2 = fmaxf(rowm[r2], tm2);
        float c1 = __expf(rowm[r1] - m1);
        float c2 = __expf(rowm[r2] - m2);
        float s1a = 0.f, s2a = 0.f;
#pragma unroll
        for (int nt = 0; nt < 2; nt++) {
            int tts = wn2 + nt * 8 + tg * 2;
            float p0 = __expf(l[nt][0] - m1);
            float p1 = __expf(l[nt][1] - m1);
            float p2 = __expf(l[nt][2] - m2);
            float p3 = __expf(l[nt][3] - m2);
            Pt[r1 * QPITCH + tts]     = f2tf32(p0);
            Pt[r1 * QPITCH + tts + 1] = f2tf32(p1);
            Pt[r2 * QPITCH + tts]     = f2tf32(p2);
            Pt[r2 * QPITCH + tts + 1] = f2tf32(p3);
            s1a += p0 + p1;
            s2a += p2 + p3;
        }
        s1a += __shfl_xor_sync(0xffffffffu, s1a, 1);
        s1a += __shfl_xor_sync(0xffffffffu, s1a, 2);
        s2a += __shfl_xor_sync(0xffffffffu, s2a, 1);
        s2a += __shfl_xor_sync(0xffffffffu, s2a, 2);
        if (tg == 0) { parts[r1 * 4 + wi] = s1a; parts[r2 * 4 + wi] = s2a; }
#pragma unroll
        for (int nt = 0; nt < 2; nt++) {
            oacc[nt][0] *= c1; oacc[nt][1] *= c1;
            oacc[nt][2] *= c2; oacc[nt][3] *= c2;
        }
        __syncthreads();   // sync4: P + partsums ready

        // designated per-row stats update (one writer per row)
        if (wi == 0 && tg == 0) {
            rowsum[r1] = rowsum[r1] * c1 +
                parts[r1 * 4 + 0] + parts[r1 * 4 + 1] + parts[r1 * 4 + 2] + parts[r1 * 4 + 3];
            rowm[r1] = m1;
            rowsum[r2] = rowsum[r2] * c2 +
                parts[r2 * 4 + 0] + parts[r2 * 4 + 1] + parts[r2 * 4 + 2] + parts[r2 * 4 + 3];
            rowm[r2] = m2;
        }

        // P @ V accumulate
#pragma unroll
        for (int k8 = 0; k8 < 64; k8 += 8) {
            uint32_t af[4];
            af[0] = Pt[r1 * QPITCH + k8 + tg];
            af[1] = Pt[r2 * QPITCH + k8 + tg];
            af[2] = Pt[r1 * QPITCH + k8 + tg + 4];
            af[3] = Pt[r2 * QPITCH + k8 + tg + 4];
#pragma unroll
            for (int nt = 0; nt < 2; nt++) {
                uint32_t bf[2];
                int col = wn2 + nt * 8 + g;
                bf[0] = Ktb[(k8 + tg) * QPITCH + col];
                bf[1] = Ktb[(k8 + tg + 4) * QPITCH + col];
                mma_tf32(oacc[nt], af, bf);
            }
        }
    }

    __syncthreads();   // rowsum final
    float inv1 = 1.f / rowsum[r1];
    float inv2 = 1.f / rowsum[r2];
    float* ob = attn + ((size_t)b * SSq + s0) * DDd + h * DKk;
#pragma unroll
    for (int nt = 0; nt < 2; nt++) {
        int c0 = wn2 + nt * 8 + tg * 2;
        *(float2*)(ob + (size_t)r1 * DDd + c0) =
            make_float2(oacc[nt][0] * inv1, oacc[nt][1] * inv1);
        *(float2*)(ob + (size_t)r2 * DDd + c0) =
            make_float2(oacc[nt][2] * inv2, oacc[nt][3] * inv2);
    }
}

// ---------------- residual + LayerNorm ----------------
__global__ void ln_kernel(const float* __restrict__ x, const float* __restrict__ res,
                          const float* __restrict__ g, const float* __restrict__ b,
                          float* __restrict__ out)
{
    int row = blockIdx.x;
    const float* xr = x + (size_t)row * DDd;
    const float* rr = res + (size_t)row * DDd;
    __shared__ float redA[33], redB[33];
    int tid = threadIdx.x;

    float loc[4];
    float s1 = 0.f, s2 = 0.f;
#pragma unroll
    for (int i = 0; i < 4; i++) {
        int d = tid + i * 256;
        float v = xr[d] + rr[d];
        loc[i] = v;
        s1 += v;
        s2 += v * v;
    }
#pragma unroll
    for (int o = 16; o; o >>= 1) {
        s1 += __shfl_xor_sync(0xffffffffu, s1, o);
        s2 += __shfl_xor_sync(0xffffffffu, s2, o);
    }
    if ((tid & 31) == 0) { redA[tid >> 5] = s1; redB[tid >> 5] = s2; }
    __syncthreads();
    if (tid < 32) {
        float a = (tid < 8) ? redA[tid] : 0.f;
        float c = (tid < 8) ? redB[tid] : 0.f;
#pragma unroll
        for (int o = 4; o; o >>= 1) {
            a += __shfl_xor_sync(0xffffffffu, a, o);
            c += __shfl_xor_sync(0xffffffffu, c, o);
        }
        if (tid == 0) { redA[32] = a; redB[32] = c; }
    }
    __syncthreads();
    float mu  = redA[32] * (1.f / DDd);
    float var = redB[32] * (1.f / DDd) - mu * mu;
    float rstd = rsqrtf(var + 1e-5f);
#pragma unroll
    for (int i = 0; i < 4; i++) {
        int d = tid + i * 256;
        out[(size_t)row * DDd + d] = (loc[i] - mu) * rstd * g[d] + b[d];
    }
}

// ---------------- host-side orchestration ----------------
extern "C" void kernel_launch(void* const* d_in, const int* in_sizes, int n_in,
                              void* d_out, int out_size)
{
    const float* x      = (const float*)d_in[0];
    const float* memory = (const float*)d_in[1];
    const float* Wq  = (const float*)d_in[2];
    const float* Wk  = (const float*)d_in[3];
    const float* Wv  = (const float*)d_in[4];
    const float* Wr  = (const float*)d_in[5];
    const float* Wo  = (const float*)d_in[6];
    const float* rwb = (const float*)d_in[7];
    const float* rrb = (const float*)d_in[8];
    const float* ln1g = (const float*)d_in[9];
    const float* ln1b = (const float*)d_in[10];
    const float* ln2g = (const float*)d_in[11];
    const float* ln2b = (const float*)d_in[12];
    const float* W1  = (const float*)d_in[13];
    const float* b1  = (const float*)d_in[14];
    const float* W2  = (const float*)d_in[15];
    const float* b2  = (const float*)d_in[16];
    float* out = (float*)d_out;

    float *pos, *kv, *q, *k, *v, *r, *attn, *tmp, *ff, *h, *h1;
    cudaGetSymbolAddress((void**)&pos,  g_pos);
    cudaGetSymbolAddress((void**)&kv,   g_kv);
    cudaGetSymbolAddress((void**)&q,    g_q);
    cudaGetSymbolAddress((void**)&k,    g_k);
    cudaGetSymbolAddress((void**)&v,    g_v);
    cudaGetSymbolAddress((void**)&r,    g_r);
    cudaGetSymbolAddress((void**)&attn, g_attn);
    cudaGetSymbolAddress((void**)&tmp,  g_tmp);
    cudaGetSymbolAddress((void**)&ff,   g_ff);
    cudaGetSymbolAddress((void**)&h,    g_h);
    cudaGetSymbolAddress((void**)&h1,   g_h1);

    cudaFuncSetAttribute(fused_attn, cudaFuncAttributeMaxDynamicSharedMemorySize,
                         SMEM_ATTN_BYTES);

    pos_kernel<<<(TTt * DDd + 255) / 256, 256>>>(pos);

    const float* hcur = x;
    for (int l = 0; l < LL; l++) {
        concat_kernel<<<(BB * TTt * DDd + 255) / 256, 256>>>(
            kv, memory + (size_t)l * BB * MMm * DDd, hcur);

        // q/k/v/r grouped: BM=128, BN=64 -> 768 working CTAs
        dim3 gG(DDd / 64, (BB * TTt) / 128, 4);
        grouped_qkvr<<<gG, 256>>>(hcur, kv, pos,
                                  Wq + (size_t)l * DDd * DDd, Wk + (size_t)l * DDd * DDd,
                                  Wv + (size_t)l * DDd * DDd, Wr + (size_t)l * DDd * DDd,
                                  q, k, v, r);

        // flash fused attention
        dim3 gA(SSq / SMT, BB * HHh);
        fused_attn<<<gA, 256, SMEM_ATTN_BYTES>>>(
            q, k, v, r, rwb + (size_t)l * HHh * DKk, rrb + (size_t)l * HHh * DKk, attn);

        // output projection: 64x64 tiles -> 256 CTAs
        dim3 gO(DDd / 64, (BB * SSq) / 64);
        tc_gemm_k<64, 2><<<gO, 256>>>(attn, Wo + (size_t)l * DDd * DDd, tmp,
                                      DDd, DDd, 1.f, nullptr, 0);
        ln_kernel<<<BB * SSq, 256>>>(tmp, hcur, ln1g + l * DDd, ln1b + l * DDd, h1);

        // FFN
        dim3 gF1(FFf / 64, (BB * SSq) / 128);   // 512 CTAs
        tc_gemm_k<128, 2><<<gF1, 256>>>(h1, W1 + (size_t)l * DDd * FFf, ff,
                                        FFf, DDd, 1.f, b1 + l * FFf, 1);
        dim3 gF2(DDd / 64, (BB * SSq) / 64);    // 256 CTAs
        tc_gemm_k<64, 2><<<gF2, 256>>>(ff, W2 + (size_t)l * FFf * DDd, tmp,
                                       DDd, FFf, 1.f, b2 + l * DDd, 0);

        float* hout = (l == LL - 1) ? out : h;
        ln_kernel<<<BB * SSq, 256>>>(tmp, h1, ln2g + l * DDd, ln2b + l * DDd, hout);
        hcur = h;
    }
}

// round 5
// speedup vs baseline: 1.1764x; 1.1764x over previous
#include <cuda_runtime.h>
#include <math.h>
#include <stdint.h>

// Problem dims
#define LL  4
#define BB  2
#define SSq 512
#define MMm 512
#define DDd 1024
#define HHh 16
#define DKk 64
#define FFf 4096
#define TTt (SSq + MMm)   // 1024

// ---------------- scratch ----------------
__device__ float g_pos[TTt * DDd];
__device__ float g_q  [BB * SSq * DDd];
__device__ float g_k  [BB * TTt * DDd];
__device__ float g_v  [BB * TTt * DDd];
__device__ float g_r  [TTt * DDd];
__device__ float g_attn[BB * SSq * DDd];
__device__ float g_tmp [BB * SSq * DDd];
__device__ float g_ff  [BB * SSq * FFf];
__device__ float g_h   [BB * SSq * DDd];
__device__ float g_h1  [BB * SSq * DDd];

// ---------------- PTX helpers ----------------
__device__ __forceinline__ uint32_t f2tf32(float f) {
    uint32_t u;
    asm("cvt.rna.tf32.f32 %0, %1;" : "=r"(u) : "f"(f));
    return u;
}
__device__ __forceinline__ void mma_tf32(float c[4], const uint32_t a[4], const uint32_t b[2]) {
    asm volatile(
        "mma.sync.aligned.m16n8k8.row.col.f32.tf32.tf32.f32 "
        "{%0,%1,%2,%3},{%4,%5,%6,%7},{%8,%9},{%0,%1,%2,%3};"
        : "+f"(c[0]), "+f"(c[1]), "+f"(c[2]), "+f"(c[3])
        : "r"(a[0]), "r"(a[1]), "r"(a[2]), "r"(a[3]), "r"(b[0]), "r"(b[1]));
}

// ---------------- positional encodings ----------------
__global__ void pos_kernel(float* __restrict__ pos)
{
    int idx = blockIdx.x * blockDim.x + threadIdx.x;
    if (idx >= TTt * DDd) return;
    int t = idx / DDd, d = idx % DDd;
    int j = (d < DDd / 2) ? d : d - DDd / 2;
    double invf = exp(((double)(-2 * j) / (double)DDd) * 9.210340371976184);
    double ang  = (double)(TTt - 1 - t) * invf;
    double kk   = floor(ang * 0.15915494309189535);
    float a = (float)(ang - kk * 6.283185307179586);
    pos[idx] = (d < DDd / 2) ? sinf(a) : cosf(a);
}

// ======================================================================
// GEMM core: Cg = alpha*Ag@Bg (+bias)(+relu). Pointers PRE-OFFSET to the
// tile's row/col block. BM x (NWN*32), BK=16, 256 threads, tf32 at store.
// ======================================================================
template<int BM, int NWN>
__device__ __forceinline__ void gemm_core(
    const float* __restrict__ Ag, const float* __restrict__ Bg, float* __restrict__ Cg,
    int N, int K, float alpha, const float* __restrict__ biasg, int relu)
{
    constexpr int BN = NWN * 32;
    constexpr int NWM = 8 / NWN;
    constexpr int WM = BM / NWM;
    constexpr int MT = WM / 16;
    constexpr int BPITCH = BN + 8;
    constexpr int NA_CH = BM / 64;
    constexpr int NB_CH = BN / 64;

    __shared__ uint32_t As[2][BM][20];
    __shared__ uint32_t Bs[2][16][BPITCH];

    int tid = threadIdx.x, lane = tid & 31, warp = tid >> 5;
    int g = lane >> 2, tg = lane & 3;
    int warp_m = warp % NWM, warp_n = warp / NWM;
    int wm = warp_m * WM, wn = warp_n * 32;

    float acc[MT][4][4];
#pragma unroll
    for (int mt = 0; mt < MT; mt++)
#pragma unroll
        for (int nt = 0; nt < 4; nt++)
#pragma unroll
            for (int i = 0; i < 4; i++) acc[mt][nt][i] = 0.f;

    int ar[NA_CH], ak[NA_CH];
#pragma unroll
    for (int j = 0; j < NA_CH; j++) {
        int c = tid + j * 256;
        ar[j] = c >> 2; ak[j] = (c & 3) * 4;
    }
    int bk[NB_CH], bn[NB_CH];
#pragma unroll
    for (int j = 0; j < NB_CH; j++) {
        int c = tid + j * 256;
        if (BN == 128) { bk[j] = c >> 5; bn[j] = (c & 31) * 4; }
        else           { bk[j] = c >> 4; bn[j] = (c & 15) * 4; }
    }

    int nk = K / 16;
    float4 sA[NA_CH], sB[NB_CH];

#pragma unroll
    for (int j = 0; j < NA_CH; j++)
        sA[j] = *(const float4*)(Ag + (size_t)ar[j] * K + ak[j]);
#pragma unroll
    for (int j = 0; j < NB_CH; j++)
        sB[j] = *(const float4*)(Bg + (size_t)bk[j] * N + bn[j]);
#pragma unroll
    for (int j = 0; j < NA_CH; j++) {
        uint4 u = make_uint4(f2tf32(sA[j].x), f2tf32(sA[j].y), f2tf32(sA[j].z), f2tf32(sA[j].w));
        *(uint4*)&As[0][ar[j]][ak[j]] = u;
    }
#pragma unroll
    for (int j = 0; j < NB_CH; j++) {
        uint4 u = make_uint4(f2tf32(sB[j].x), f2tf32(sB[j].y), f2tf32(sB[j].z), f2tf32(sB[j].w));
        *(uint4*)&Bs[0][bk[j]][bn[j]] = u;
    }
    __syncthreads();

    for (int kt = 0; kt < nk; kt++) {
        int buf = kt & 1;
        bool more = (kt + 1 < nk);
        if (more) {
#pragma unroll
            for (int j = 0; j < NA_CH; j++)
                sA[j] = *(const float4*)(Ag + (size_t)ar[j] * K + (kt + 1) * 16 + ak[j]);
#pragma unroll
            for (int j = 0; j < NB_CH; j++)
                sB[j] = *(const float4*)(Bg + (size_t)((kt + 1) * 16 + bk[j]) * N + bn[j]);
        }

#pragma unroll
        for (int ks = 0; ks < 2; ks++) {
            uint32_t af[MT][4], bf[4][2];
#pragma unroll
            for (int mt = 0; mt < MT; mt++) {
                int row = wm + mt * 16;
                af[mt][0] = As[buf][row + g][ks * 8 + tg];
                af[mt][1] = As[buf][row + g + 8][ks * 8 + tg];
                af[mt][2] = As[buf][row + g][ks * 8 + tg + 4];
                af[mt][3] = As[buf][row + g + 8][ks * 8 + tg + 4];
            }
#pragma unroll
            for (int nt = 0; nt < 4; nt++) {
                int col = wn + nt * 8 + g;
                bf[nt][0] = Bs[buf][ks * 8 + tg][col];
                bf[nt][1] = Bs[buf][ks * 8 + tg + 4][col];
            }
#pragma unroll
            for (int mt = 0; mt < MT; mt++)
#pragma unroll
                for (int nt = 0; nt < 4; nt++) mma_tf32(acc[mt][nt], af[mt], bf[nt]);
        }

        if (more) {
            int nb = buf ^ 1;
#pragma unroll
            for (int j = 0; j < NA_CH; j++) {
                uint4 u = make_uint4(f2tf32(sA[j].x), f2tf32(sA[j].y), f2tf32(sA[j].z), f2tf32(sA[j].w));
                *(uint4*)&As[nb][ar[j]][ak[j]] = u;
            }
#pragma unroll
            for (int j = 0; j < NB_CH; j++) {
                uint4 u = make_uint4(f2tf32(sB[j].x), f2tf32(sB[j].y), f2tf32(sB[j].z), f2tf32(sB[j].w));
                *(uint4*)&Bs[nb][bk[j]][bn[j]] = u;
            }
            __syncthreads();
        }
    }

#pragma unroll
    for (int mt = 0; mt < MT; mt++) {
#pragma unroll
        for (int nt = 0; nt < 4; nt++) {
            int row = wm + mt * 16 + g;
            int col = wn + nt * 8 + tg * 2;
            float bx0 = 0.f, bx1 = 0.f;
            if (biasg) { bx0 = biasg[col]; bx1 = biasg[col + 1]; }
            float v0 = acc[mt][nt][0] * alpha + bx0;
            float v1 = acc[mt][nt][1] * alpha + bx1;
            float v2 = acc[mt][nt][2] * alpha + bx0;
            float v3 = acc[mt][nt][3] * alpha + bx1;
            if (relu) {
                v0 = fmaxf(v0, 0.f); v1 = fmaxf(v1, 0.f);
                v2 = fmaxf(v2, 0.f); v3 = fmaxf(v3, 0.f);
            }
            *(float2*)(Cg + (size_t)row * N + col)       = make_float2(v0, v1);
            *(float2*)(Cg + (size_t)(row + 8) * N + col) = make_float2(v2, v3);
        }
    }
}

template<int BM, int NWN>
__global__ void __launch_bounds__(256) tc_gemm_k(
    const float* __restrict__ A, const float* __restrict__ B, float* __restrict__ C,
    int N, int K, float alpha, const float* __restrict__ bias, int relu)
{
    constexpr int BN = NWN * 32;
    const float* Ag = A + (size_t)blockIdx.y * BM * K;
    const float* Bg = B + (size_t)blockIdx.x * BN;
    float* Cg = C + (size_t)blockIdx.y * BM * N + (size_t)blockIdx.x * BN;
    const float* bg = bias ? bias + (size_t)blockIdx.x * BN : nullptr;
    gemm_core<BM, NWN>(Ag, Bg, Cg, N, K, alpha, bg, relu);
}

// grouped q/k/v/r projections with concat folded into the A pointer.
// BM=128, BN=128. grid (8, 16, 4); z=0 (q) and z=3 (r) mask y>=8.
__global__ void __launch_bounds__(256) grouped_qkvr(
    const float* __restrict__ hc, const float* __restrict__ mem, const float* __restrict__ pos,
    const float* __restrict__ Wq, const float* __restrict__ Wk,
    const float* __restrict__ Wv, const float* __restrict__ Wr,
    float* __restrict__ q, float* __restrict__ k, float* __restrict__ v, float* __restrict__ r)
{
    int z = blockIdx.z, by = blockIdx.y;
    const float* Ag; const float* B; float* C; float alpha = 1.f;
    if (z == 0) {
        if (by >= 8) return;
        Ag = hc + (size_t)by * 128 * DDd; B = Wq; C = q + (size_t)by * 128 * DDd;
        alpha = 0.125f;
    } else if (z == 3) {
        if (by >= 8) return;
        Ag = pos + (size_t)by * 128 * DDd; B = Wr; C = r + (size_t)by * 128 * DDd;
    } else {
        // kv rows: b = row0>>10, t0 = row0 & 1023; 128-blocks never straddle the 512 split
        int row0 = by * 128;
        int b = row0 >> 10, t0 = row0 & 1023;
        Ag = (t0 < MMm) ? mem + ((size_t)b * MMm + t0) * DDd
                        : hc  + ((size_t)b * SSq + (t0 - MMm)) * DDd;
        if (z == 1) { B = Wk; C = k + (size_t)by * 128 * DDd; }
        else        { B = Wv; C = v + (size_t)by * 128 * DDd; }
    }
    const float* Bg = B + (size_t)blockIdx.x * 128;
    float* Cg = C + (size_t)blockIdx.x * 128;
    gemm_core<128, 4>(Ag, Bg, Cg, DDd, DDd, alpha, nullptr, 0);
}

// ======================================================================
// Flash fused attention (unchanged from R4): content + rel(window) + mask
// + online softmax + P@V. CTA = 32 query rows of one (b,h). 8 warps.
// ======================================================================
#define SMT   32
#define TN    64
#define QPITCH 68
#define WPITCH 100
#define SMEM_ATTN_FLOATS (2*SMT*QPITCH + 64*QPITCH + 96*QPITCH + SMT*WPITCH + SMT*QPITCH + 128 + 128 + 32 + 32)
#define SMEM_ATTN_BYTES  (SMEM_ATTN_FLOATS * 4)

__global__ void __launch_bounds__(256) fused_attn(
    const float* __restrict__ q, const float* __restrict__ k, const float* __restrict__ v,
    const float* __restrict__ r, const float* __restrict__ rwb, const float* __restrict__ rrb,
    float* __restrict__ attn)
{
    extern __shared__ float sm[];
    uint32_t* Qcb  = (uint32_t*)sm;
    uint32_t* Qrb  = Qcb + SMT * QPITCH;
    uint32_t* Ktb  = Qrb + SMT * QPITCH;
    uint32_t* Rwb  = Ktb + 64 * QPITCH;
    float* QRW     = (float*)(Rwb + 96 * QPITCH);
    uint32_t* Pt   = (uint32_t*)(QRW + SMT * WPITCH);
    float* partm   = (float*)(Pt + SMT * QPITCH);
    float* parts   = partm + 128;
    float* rowm    = parts + 128;
    float* rowsum  = rowm + 32;

    int tid = threadIdx.x, lane = tid & 31, warp = tid >> 5;
    int g = lane >> 2, tg = lane & 3;
    int s0 = blockIdx.x * SMT;
    int b = blockIdx.y >> 4, h = blockIdx.y & 15;

    const float* qb = q + (size_t)b * SSq * DDd + h * DKk;
    const float* kb = k + (size_t)b * TTt * DDd + h * DKk;
    const float* vb = v + (size_t)b * TTt * DDd + h * DKk;
    const float* rb = r + h * DKk;
    const float* wbv = rwb + h * DKk;
    const float* rbv = rrb + h * DKk;

#pragma unroll
    for (int j = 0; j < 2; j++) {
        int c = tid + j * 256;
        int row = c >> 4, k0 = (c & 15) * 4;
        float4 qv = *(const float4*)(qb + (size_t)(s0 + row) * DDd + k0);
        float4 w4 = *(const float4*)(wbv + k0);
        float4 r4 = *(const float4*)(rbv + k0);
        Qcb[row * QPITCH + k0 + 0] = f2tf32(qv.x + w4.x);
        Qcb[row * QPITCH + k0 + 1] = f2tf32(qv.y + w4.y);
        Qcb[row * QPITCH + k0 + 2] = f2tf32(qv.z + w4.z);
        Qcb[row * QPITCH + k0 + 3] = f2tf32(qv.w + w4.w);
        Qrb[row * QPITCH + k0 + 0] = f2tf32(qv.x + r4.x);
        Qrb[row * QPITCH + k0 + 1] = f2tf32(qv.y + r4.y);
        Qrb[row * QPITCH + k0 + 2] = f2tf32(qv.z + r4.z);
        Qrb[row * QPITCH + k0 + 3] = f2tf32(qv.w + r4.w);
    }
    if (tid < 32) { rowm[tid] = -1e30f; rowsum[tid] = 0.f; }

    int ntiles = (s0 + 543) / 64 + 1;
    int wm2 = (warp & 1) * 16;
    int wn2 = (warp >> 1) * 16;
    int wn3 = (warp >> 1) * 24;
    int wi  = warp >> 1;
    int r1 = wm2 + g, r2 = r1 + 8;

    float oacc[2][4];
#pragma unroll
    for (int nt = 0; nt < 2; nt++)
#pragma unroll
        for (int i = 0; i < 4; i++) oacc[nt][i] = 0.f;

    for (int it = 0; it < ntiles; it++) {
        int t0 = it * TN;
        int jb = t0 - s0 + 480;
        __syncthreads();

#pragma unroll
        for (int j = 0; j < 4; j++) {
            int c = tid + j * 256;
            int row = c >> 4, k0 = (c & 15) * 4;
            float4 kv4 = *(const float4*)(kb + (size_t)(t0 + row) * DDd + k0);
            Ktb[row * QPITCH + k0 + 0] = f2tf32(kv4.x);
            Ktb[row * QPITCH + k0 + 1] = f2tf32(kv4.y);
            Ktb[row * QPITCH + k0 + 2] = f2tf32(kv4.z);
            Ktb[row * QPITCH + k0 + 3] = f2tf32(kv4.w);
        }
#pragma unroll
        for (int j = 0; j < 6; j++) {
            int c = tid + j * 256;
            int row = c >> 4, k0 = (c & 15) * 4;
            int jg = jb + row; if (jg > TTt - 1) jg = TTt - 1;
            float4 rv4 = *(const float4*)(rb + (size_t)jg * DDd + k0);
            Rwb[row * QPITCH + k0 + 0] = f2tf32(rv4.x);
            Rwb[row * QPITCH + k0 + 1] = f2tf32(rv4.y);
            Rwb[row * QPITCH + k0 + 2] = f2tf32(rv4.z);
            Rwb[row * QPITCH + k0 + 3] = f2tf32(rv4.w);
        }
        __syncthreads();

        float ca[2][4], ra[3][4];
#pragma unroll
        for (int nt = 0; nt < 2; nt++)
#pragma unroll
            for (int i = 0; i < 4; i++) ca[nt][i] = 0.f;
#pragma unroll
        for (int nt = 0; nt < 3; nt++)
#pragma unroll
            for (int i = 0; i < 4; i++) ra[nt][i] = 0.f;

#pragma unroll
        for (int k8 = 0; k8 < 64; k8 += 8) {
            uint32_t af[4], afr[4];
            af[0]  = Qcb[(wm2 + g) * QPITCH + k8 + tg];
            af[1]  = Qcb[(wm2 + g + 8) * QPITCH + k8 + tg];
            af[2]  = Qcb[(wm2 + g) * QPITCH + k8 + tg + 4];
            af[3]  = Qcb[(wm2 + g + 8) * QPITCH + k8 + tg + 4];
            afr[0] = Qrb[(wm2 + g) * QPITCH + k8 + tg];
            afr[1] = Qrb[(wm2 + g + 8) * QPITCH + k8 + tg];
            afr[2] = Qrb[(wm2 + g) * QPITCH + k8 + tg + 4];
            afr[3] = Qrb[(wm2 + g + 8) * QPITCH + k8 + tg + 4];
#pragma unroll
            for (int nt = 0; nt < 2; nt++) {
                uint32_t bf[2];
                int col = wn2 + nt * 8 + g;
                bf[0] = Ktb[col * QPITCH + k8 + tg];
                bf[1] = Ktb[col * QPITCH + k8 + tg + 4];
                mma_tf32(ca[nt], af, bf);
            }
#pragma unroll
            for (int nt = 0; nt < 3; nt++) {
                uint32_t bf[2];
                int col = wn3 + nt * 8 + g;
                bf[0] = Rwb[col * QPITCH + k8 + tg];
                bf[1] = Rwb[col * QPITCH + k8 + tg + 4];
                mma_tf32(ra[nt], afr, bf);
            }
        }
#pragma unroll
        for (int nt = 0; nt < 3; nt++) {
            int c0 = wn3 + nt * 8 + tg * 2;
            QRW[r1 * WPITCH + c0]     = ra[nt][0];
            QRW[r1 * WPITCH + c0 + 1] = ra[nt][1];
            QRW[r2 * WPITCH + c0]     = ra[nt][2];
            QRW[r2 * WPITCH + c0 + 1] = ra[nt][3];
        }
        __syncthreads();

        float l[2][4];
#pragma unroll
        for (int nt = 0; nt < 2; nt++) {
            int tts = wn2 + nt * 8 + tg * 2;
#pragma unroll
            for (int i = 0; i < 4; i++) {
                int si = wm2 + g + ((i >= 2) ? 8 : 0);
                int tt = tts + (i & 1);
                int t = t0 + tt, s = s0 + si;
                l[nt][i] = (t - s <= MMm)
                    ? ca[nt][i] + QRW[si * WPITCH + tt + (SMT - 1) - si]
                    : -1e30f;
            }
        }
        float mx1 = fmaxf(fmaxf(l[0][0], l[0][1]), fmaxf(l[1][0], l[1][1]));
        float mx2 = fmaxf(fmaxf(l[0][2], l[0][3]), fmaxf(l[1][2], l[1][3]));
        mx1 = fmaxf(mx1, __shfl_xor_sync(0xffffffffu, mx1, 1));
        mx1 = fmaxf(mx1, __shfl_xor_sync(0xffffffffu, mx1, 2));
        mx2 = fmaxf(mx2, __shfl_xor_sync(0xffffffffu, mx2, 1));
        mx2 = fmaxf(mx2, __shfl_xor_sync(0xffffffffu, mx2, 2));
        if (tg == 0) { partm[r1 * 4 + wi] = mx1; partm[r2 * 4 + wi] = mx2; }

#pragma unroll
        for (int j = 0; j < 4; j++) {
            int c = tid + j * 256;
            int row = c >> 4, k0 = (c & 15) * 4;
            float4 vv4 = *(const float4*)(vb + (size_t)(t0 + row) * DDd + k0);
            Ktb[row * QPITCH + k0 + 0] = f2tf32(vv4.x);
            Ktb[row * QPITCH + k0 + 1] = f2tf32(vv4.y);
            Ktb[row * QPITCH + k0 + 2] = f2tf32(vv4.z);
            Ktb[row * QPITCH + k0 + 3] = f2tf32(vv4.w);
        }
        __syncthreads();

        float tm1 = fmaxf(fmaxf(partm[r1 * 4 + 0], partm[r1 * 4 + 1]),
                          fmaxf(partm[r1 * 4 + 2], partm[r1 * 4 + 3]));
        float tm2 = fmaxf(fmaxf(partm[r2 * 4 + 0], partm[r2 * 4 + 1]),
                          fmaxf(partm[r2 * 4 + 2], partm[r2 * 4 + 3]));
        float m1 = fmaxf(rowm[r1], tm1);
        float m2 = fmaxf(rowm[r2], tm2);
        float c1 = __expf(rowm[r1] - m1);
        float c2 = __expf(rowm[r2] - m2);
        float s1a = 0.f, s2a = 0.f;
#pragma unroll
        for (int nt = 0; nt < 2; nt++) {
            int tts = wn2 + nt * 8 + tg * 2;
            float p0 = __expf(l[nt][0] - m1);
            float p1 = __expf(l[nt][1] - m1);
            float p2 = __expf(l[nt][2] - m2);
            float p3 = __expf(l[nt][3] - m2);
            Pt[r1 * QPITCH + tts]     = f2tf32(p0);
            Pt[r1 * QPITCH + tts + 1] = f2tf32(p1);
            Pt[r2 * QPITCH + tts]     = f2tf32(p2);
            Pt[r2 * QPITCH + tts + 1] = f2tf32(p3);
            s1a += p0 + p1;
            s2a += p2 + p3;
        }
        s1a += __shfl_xor_sync(0xffffffffu, s1a, 1);
        s1a += __shfl_xor_sync(0xffffffffu, s1a, 2);
        s2a += __shfl_xor_sync(0xffffffffu, s2a, 1);
        s2a += __shfl_xor_sync(0xffffffffu, s2a, 2);
        if (tg == 0) { parts[r1 * 4 + wi] = s1a; parts[r2 * 4 + wi] = s2a; }
#pragma unroll
        for (int nt = 0; nt < 2; nt++) {
            oacc[nt][0] *= c1; oacc[nt][1] *= c1;
            oacc[nt][2] *= c2; oacc[nt][3] *= c2;
        }
        __syncthreads();

        if (wi == 0 && tg == 0) {
            rowsum[r1] = rowsum[r1] * c1 +
                parts[r1 * 4 + 0] + parts[r1 * 4 + 1] + parts[r1 * 4 + 2] + parts[r1 * 4 + 3];
            rowm[r1] = m1;
            rowsum[r2] = rowsum[r2] * c2 +
                parts[r2 * 4 + 0] + parts[r2 * 4 + 1] + parts[r2 * 4 + 2] + parts[r2 * 4 + 3];
            rowm[r2] = m2;
        }

#pragma unroll
        for (int k8 = 0; k8 < 64; k8 += 8) {
            uint32_t af[4];
            af[0] = Pt[r1 * QPITCH + k8 + tg];
            af[1] = Pt[r2 * QPITCH + k8 + tg];
            af[2] = Pt[r1 * QPITCH + k8 + tg + 4];
            af[3] = Pt[r2 * QPITCH + k8 + tg + 4];
#pragma unroll
            for (int nt = 0; nt < 2; nt++) {
                uint32_t bf[2];
                int col = wn2 + nt * 8 + g;
                bf[0] = Ktb[(k8 + tg) * QPITCH + col];
                bf[1] = Ktb[(k8 + tg + 4) * QPITCH + col];
                mma_tf32(oacc[nt], af, bf);
            }
        }
    }

    __syncthreads();
    float inv1 = 1.f / rowsum[r1];
    float inv2 = 1.f / rowsum[r2];
    float* ob = attn + ((size_t)b * SSq + s0) * DDd + h * DKk;
#pragma unroll
    for (int nt = 0; nt < 2; nt++) {
        int c0 = wn2 + nt * 8 + tg * 2;
        *(float2*)(ob + (size_t)r1 * DDd + c0) =
            make_float2(oacc[nt][0] * inv1, oacc[nt][1] * inv1);
        *(float2*)(ob + (size_t)r2 * DDd + c0) =
            make_float2(oacc[nt][2] * inv2, oacc[nt][3] * inv2);
    }
}

// ---------------- residual + LayerNorm ----------------
__global__ void ln_kernel(const float* __restrict__ x, const float* __restrict__ res,
                          const float* __restrict__ g, const float* __restrict__ b,
                          float* __restrict__ out)
{
    int row = blockIdx.x;
    const float* xr = x + (size_t)row * DDd;
    const float* rr = res + (size_t)row * DDd;
    __shared__ float redA[33], redB[33];
    int tid = threadIdx.x;

    float loc[4];
    float s1 = 0.f, s2 = 0.f;
#pragma unroll
    for (int i = 0; i < 4; i++) {
        int d = tid + i * 256;
        float v = xr[d] + rr[d];
        loc[i] = v;
        s1 += v;
        s2 += v * v;
    }
#pragma unroll
    for (int o = 16; o; o >>= 1) {
        s1 += __shfl_xor_sync(0xffffffffu, s1, o);
        s2 += __shfl_xor_sync(0xffffffffu, s2, o);
    }
    if ((tid & 31) == 0) { redA[tid >> 5] = s1; redB[tid >> 5] = s2; }
    __syncthreads();
    if (tid < 32) {
        float a = (tid < 8) ? redA[tid] : 0.f;
        float c = (tid < 8) ? redB[tid] : 0.f;
#pragma unroll
        for (int o = 4; o; o >>= 1) {
            a += __shfl_xor_sync(0xffffffffu, a, o);
            c += __shfl_xor_sync(0xffffffffu, c, o);
        }
        if (tid == 0) { redA[32] = a; redB[32] = c; }
    }
    __syncthreads();
    float mu  = redA[32] * (1.f / DDd);
    float var = redB[32] * (1.f / DDd) - mu * mu;
    float rstd = rsqrtf(var + 1e-5f);
#pragma unroll
    for (int i = 0; i < 4; i++) {
        int d = tid + i * 256;
        out[(size_t)row * DDd + d] = (loc[i] - mu) * rstd * g[d] + b[d];
    }
}

// ---------------- host-side orchestration ----------------
extern "C" void kernel_launch(void* const* d_in, const int* in_sizes, int n_in,
                              void* d_out, int out_size)
{
    const float* x      = (const float*)d_in[0];
    const float* memory = (const float*)d_in[1];
    const float* Wq  = (const float*)d_in[2];
    const float* Wk  = (const float*)d_in[3];
    const float* Wv  = (const float*)d_in[4];
    const float* Wr  = (const float*)d_in[5];
    const float* Wo  = (const float*)d_in[6];
    const float* rwb = (const float*)d_in[7];
    const float* rrb = (const float*)d_in[8];
    const float* ln1g = (const float*)d_in[9];
    const float* ln1b = (const float*)d_in[10];
    const float* ln2g = (const float*)d_in[11];
    const float* ln2b = (const float*)d_in[12];
    const float* W1  = (const float*)d_in[13];
    const float* b1  = (const float*)d_in[14];
    const float* W2  = (const float*)d_in[15];
    const float* b2  = (const float*)d_in[16];
    float* out = (float*)d_out;

    float *pos, *q, *k, *v, *r, *attn, *tmp, *ff, *h, *h1;
    cudaGetSymbolAddress((void**)&pos,  g_pos);
    cudaGetSymbolAddress((void**)&q,    g_q);
    cudaGetSymbolAddress((void**)&k,    g_k);
    cudaGetSymbolAddress((void**)&v,    g_v);
    cudaGetSymbolAddress((void**)&r,    g_r);
    cudaGetSymbolAddress((void**)&attn, g_attn);
    cudaGetSymbolAddress((void**)&tmp,  g_tmp);
    cudaGetSymbolAddress((void**)&ff,   g_ff);
    cudaGetSymbolAddress((void**)&h,    g_h);
    cudaGetSymbolAddress((void**)&h1,   g_h1);

    cudaFuncSetAttribute(fused_attn, cudaFuncAttributeMaxDynamicSharedMemorySize,
                         SMEM_ATTN_BYTES);

    pos_kernel<<<(TTt * DDd + 255) / 256, 256>>>(pos);

    const float* hcur = x;
    for (int l = 0; l < LL; l++) {
        // q/k/v/r grouped, 128x128 tiles, concat folded into A-pointer
        dim3 gG(DDd / 128, (BB * TTt) / 128, 4);   // (8, 16, 4), 384 working CTAs
        grouped_qkvr<<<gG, 256>>>(hcur, memory + (size_t)l * BB * MMm * DDd, pos,
                                  Wq + (size_t)l * DDd * DDd, Wk + (size_t)l * DDd * DDd,
                                  Wv + (size_t)l * DDd * DDd, Wr + (size_t)l * DDd * DDd,
                                  q, k, v, r);

        // flash fused attention
        dim3 gA(SSq / SMT, BB * HHh);
        fused_attn<<<gA, 256, SMEM_ATTN_BYTES>>>(
            q, k, v, r, rwb + (size_t)l * HHh * DKk, rrb + (size_t)l * HHh * DKk, attn);

        // output projection: BM=64, BN=128 -> 128 CTAs
        dim3 gO(DDd / 128, (BB * SSq) / 64);
        tc_gemm_k<64, 4><<<gO, 256>>>(attn, Wo + (size_t)l * DDd * DDd, tmp,
                                      DDd, DDd, 1.f, nullptr, 0);
        ln_kernel<<<BB * SSq, 256>>>(tmp, hcur, ln1g + l * DDd, ln1b + l * DDd, h1);

        // FFN
        dim3 gF1(FFf / 128, (BB * SSq) / 128);     // 256 CTAs
        tc_gemm_k<128, 4><<<gF1, 256>>>(h1, W1 + (size_t)l * DDd * FFf, ff,
                                        FFf, DDd, 1.f, b1 + l * FFf, 1);
        dim3 gF2(DDd / 128, (BB * SSq) / 64);      // 128 CTAs
        tc_gemm_k<64, 4><<<gF2, 256>>>(ff, W2 + (size_t)l * FFf * DDd, tmp,
                                       DDd, FFf, 1.f, b2 + l * DDd, 0);

        float* hout = (l == LL - 1) ? out : h;
        ln_kernel<<<BB * SSq, 256>>>(tmp, h1, ln2g + l * DDd, ln2b + l * DDd, hout);
        hcur = h;
    }
}

// round 6
// speedup vs baseline: 1.4263x; 1.2125x over previous
#include <cuda_runtime.h>
#include <math.h>
#include <stdint.h>

// Problem dims
#define LL  4
#define BB  2
#define SSq 512
#define MMm 512
#define DDd 1024
#define HHh 16
#define DKk 64
#define FFf 4096
#define TTt (SSq + MMm)   // 1024

// ---------------- scratch ----------------
__device__ float g_pos[TTt * DDd];
__device__ float g_q  [BB * SSq * DDd];
__device__ float g_k  [BB * TTt * DDd];
__device__ float g_v  [BB * TTt * DDd];
__device__ float g_r  [TTt * DDd];
__device__ float g_attn[BB * SSq * DDd];
__device__ float g_tmp [BB * SSq * DDd];
__device__ float g_tmp2[BB * SSq * DDd];
__device__ float g_ff  [BB * SSq * FFf];
__device__ float g_h   [BB * SSq * DDd];
__device__ float g_h1  [BB * SSq * DDd];

// ---------------- PTX helpers ----------------
__device__ __forceinline__ uint32_t f2tf32(float f) {
    uint32_t u;
    asm("cvt.rna.tf32.f32 %0, %1;" : "=r"(u) : "f"(f));
    return u;
}
__device__ __forceinline__ void mma_tf32(float c[4], const uint32_t a[4], const uint32_t b[2]) {
    asm volatile(
        "mma.sync.aligned.m16n8k8.row.col.f32.tf32.tf32.f32 "
        "{%0,%1,%2,%3},{%4,%5,%6,%7},{%8,%9},{%0,%1,%2,%3};"
        : "+f"(c[0]), "+f"(c[1]), "+f"(c[2]), "+f"(c[3])
        : "r"(a[0]), "r"(a[1]), "r"(a[2]), "r"(a[3]), "r"(b[0]), "r"(b[1]));
}

// ---------------- positional encodings (sin+cos per thread) ----------------
__global__ void pos_kernel(float* __restrict__ pos)
{
    int idx = blockIdx.x * blockDim.x + threadIdx.x;
    if (idx >= TTt * (DDd / 2)) return;
    int t = idx / (DDd / 2), j = idx % (DDd / 2);
    double invf = exp(((double)(-2 * j) / (double)DDd) * 9.210340371976184);
    double ang  = (double)(TTt - 1 - t) * invf;
    double kk   = floor(ang * 0.15915494309189535);
    float a = (float)(ang - kk * 6.283185307179586);
    pos[(size_t)t * DDd + j]            = sinf(a);
    pos[(size_t)t * DDd + j + DDd / 2]  = cosf(a);
}

// ======================================================================
// GEMM core: Cg = alpha*Ag@Bg (+bias)(+relu). Pointers PRE-OFFSET.
// BM x (NWN*32), BK=16, 256 threads, tf32 at smem store.
// lda = A row stride (>= K for split-K column slices).
// ======================================================================
template<int BM, int NWN>
__device__ __forceinline__ void gemm_core(
    const float* __restrict__ Ag, const float* __restrict__ Bg, float* __restrict__ Cg,
    int N, int K, int lda, float alpha, const float* __restrict__ biasg, int relu)
{
    constexpr int BN = NWN * 32;
    constexpr int NWM = 8 / NWN;
    constexpr int WM = BM / NWM;
    constexpr int MT = WM / 16;
    constexpr int BPITCH = BN + 8;
    constexpr int NA_CH = BM / 64;
    constexpr int NB_CH = BN / 64;

    __shared__ uint32_t As[2][BM][20];
    __shared__ uint32_t Bs[2][16][BPITCH];

    int tid = threadIdx.x, lane = tid & 31, warp = tid >> 5;
    int g = lane >> 2, tg = lane & 3;
    int warp_m = warp % NWM, warp_n = warp / NWM;
    int wm = warp_m * WM, wn = warp_n * 32;

    float acc[MT][4][4];
#pragma unroll
    for (int mt = 0; mt < MT; mt++)
#pragma unroll
        for (int nt = 0; nt < 4; nt++)
#pragma unroll
            for (int i = 0; i < 4; i++) acc[mt][nt][i] = 0.f;

    int ar[NA_CH], ak[NA_CH];
#pragma unroll
    for (int j = 0; j < NA_CH; j++) {
        int c = tid + j * 256;
        ar[j] = c >> 2; ak[j] = (c & 3) * 4;
    }
    int bk[NB_CH], bn[NB_CH];
#pragma unroll
    for (int j = 0; j < NB_CH; j++) {
        int c = tid + j * 256;
        if (BN == 128) { bk[j] = c >> 5; bn[j] = (c & 31) * 4; }
        else           { bk[j] = c >> 4; bn[j] = (c & 15) * 4; }
    }

    int nk = K / 16;
    float4 sA[NA_CH], sB[NB_CH];

#pragma unroll
    for (int j = 0; j < NA_CH; j++)
        sA[j] = *(const float4*)(Ag + (size_t)ar[j] * lda + ak[j]);
#pragma unroll
    for (int j = 0; j < NB_CH; j++)
        sB[j] = *(const float4*)(Bg + (size_t)bk[j] * N + bn[j]);
#pragma unroll
    for (int j = 0; j < NA_CH; j++) {
        uint4 u = make_uint4(f2tf32(sA[j].x), f2tf32(sA[j].y), f2tf32(sA[j].z), f2tf32(sA[j].w));
        *(uint4*)&As[0][ar[j]][ak[j]] = u;
    }
#pragma unroll
    for (int j = 0; j < NB_CH; j++) {
        uint4 u = make_uint4(f2tf32(sB[j].x), f2tf32(sB[j].y), f2tf32(sB[j].z), f2tf32(sB[j].w));
        *(uint4*)&Bs[0][bk[j]][bn[j]] = u;
    }
    __syncthreads();

    for (int kt = 0; kt < nk; kt++) {
        int buf = kt & 1;
        bool more = (kt + 1 < nk);
        if (more) {
#pragma unroll
            for (int j = 0; j < NA_CH; j++)
                sA[j] = *(const float4*)(Ag + (size_t)ar[j] * lda + (kt + 1) * 16 + ak[j]);
#pragma unroll
            for (int j = 0; j < NB_CH; j++)
                sB[j] = *(const float4*)(Bg + (size_t)((kt + 1) * 16 + bk[j]) * N + bn[j]);
        }

#pragma unroll
        for (int ks = 0; ks < 2; ks++) {
            uint32_t af[MT][4], bf[4][2];
#pragma unroll
            for (int mt = 0; mt < MT; mt++) {
                int row = wm + mt * 16;
                af[mt][0] = As[buf][row + g][ks * 8 + tg];
                af[mt][1] = As[buf][row + g + 8][ks * 8 + tg];
                af[mt][2] = As[buf][row + g][ks * 8 + tg + 4];
                af[mt][3] = As[buf][row + g + 8][ks * 8 + tg + 4];
            }
#pragma unroll
            for (int nt = 0; nt < 4; nt++) {
                int col = wn + nt * 8 + g;
                bf[nt][0] = Bs[buf][ks * 8 + tg][col];
                bf[nt][1] = Bs[buf][ks * 8 + tg + 4][col];
            }
#pragma unroll
            for (int mt = 0; mt < MT; mt++)
#pragma unroll
                for (int nt = 0; nt < 4; nt++) mma_tf32(acc[mt][nt], af[mt], bf[nt]);
        }

        if (more) {
            int nb = buf ^ 1;
#pragma unroll
            for (int j = 0; j < NA_CH; j++) {
                uint4 u = make_uint4(f2tf32(sA[j].x), f2tf32(sA[j].y), f2tf32(sA[j].z), f2tf32(sA[j].w));
                *(uint4*)&As[nb][ar[j]][ak[j]] = u;
            }
#pragma unroll
            for (int j = 0; j < NB_CH; j++) {
                uint4 u = make_uint4(f2tf32(sB[j].x), f2tf32(sB[j].y), f2tf32(sB[j].z), f2tf32(sB[j].w));
                *(uint4*)&Bs[nb][bk[j]][bn[j]] = u;
            }
            __syncthreads();
        }
    }

#pragma unroll
    for (int mt = 0; mt < MT; mt++) {
#pragma unroll
        for (int nt = 0; nt < 4; nt++) {
            int row = wm + mt * 16 + g;
            int col = wn + nt * 8 + tg * 2;
            float bx0 = 0.f, bx1 = 0.f;
            if (biasg) { bx0 = biasg[col]; bx1 = biasg[col + 1]; }
            float v0 = acc[mt][nt][0] * alpha + bx0;
            float v1 = acc[mt][nt][1] * alpha + bx1;
            float v2 = acc[mt][nt][2] * alpha + bx0;
            float v3 = acc[mt][nt][3] * alpha + bx1;
            if (relu) {
                v0 = fmaxf(v0, 0.f); v1 = fmaxf(v1, 0.f);
                v2 = fmaxf(v2, 0.f); v3 = fmaxf(v3, 0.f);
            }
            *(float2*)(Cg + (size_t)row * N + col)       = make_float2(v0, v1);
            *(float2*)(Cg + (size_t)(row + 8) * N + col) = make_float2(v2, v3);
        }
    }
}

template<int BM, int NWN>
__global__ void __launch_bounds__(256) tc_gemm_k(
    const float* __restrict__ A, const float* __restrict__ B, float* __restrict__ C,
    int N, int K, float alpha, const float* __restrict__ bias, int relu)
{
    constexpr int BN = NWN * 32;
    const float* Ag = A + (size_t)blockIdx.y * BM * K;
    const float* Bg = B + (size_t)blockIdx.x * BN;
    float* Cg = C + (size_t)blockIdx.y * BM * N + (size_t)blockIdx.x * BN;
    const float* bg = bias ? bias + (size_t)blockIdx.x * BN : nullptr;
    gemm_core<BM, NWN>(Ag, Bg, Cg, N, K, K, alpha, bg, relu);
}

// split-K=2 GEMM: z-half computes partial over K/2, writes C0 (z=0) or C1 (z=1).
// bias applied only in z=0. Downstream ln adds the partials.
template<int BM, int NWN>
__global__ void __launch_bounds__(256) tc_gemm_splitk(
    const float* __restrict__ A, const float* __restrict__ B,
    float* __restrict__ C0, float* __restrict__ C1,
    int N, int K, const float* __restrict__ bias)
{
    constexpr int BN = NWN * 32;
    int z = blockIdx.z;
    int K2 = K >> 1;
    const float* Ag = A + (size_t)blockIdx.y * BM * K + (size_t)z * K2;
    const float* Bg = B + (size_t)z * K2 * N + (size_t)blockIdx.x * BN;
    float* C = z ? C1 : C0;
    float* Cg = C + (size_t)blockIdx.y * BM * N + (size_t)blockIdx.x * BN;
    const float* bg = (bias && z == 0) ? bias + (size_t)blockIdx.x * BN : nullptr;
    gemm_core<BM, NWN>(Ag, Bg, Cg, N, K2, K, 1.f, bg, 0);
}

// grouped q/k/v/r projections with concat folded into the A pointer.
__global__ void __launch_bounds__(256) grouped_qkvr(
    const float* __restrict__ hc, const float* __restrict__ mem, const float* __restrict__ pos,
    const float* __restrict__ Wq, const float* __restrict__ Wk,
    const float* __restrict__ Wv, const float* __restrict__ Wr,
    float* __restrict__ q, float* __restrict__ k, float* __restrict__ v, float* __restrict__ r)
{
    int z = blockIdx.z, by = blockIdx.y;
    const float* Ag; const float* B; float* C; float alpha = 1.f;
    if (z == 0) {
        if (by >= 8) return;
        Ag = hc + (size_t)by * 128 * DDd; B = Wq; C = q + (size_t)by * 128 * DDd;
        alpha = 0.125f;
    } else if (z == 3) {
        if (by >= 8) return;
        Ag = pos + (size_t)by * 128 * DDd; B = Wr; C = r + (size_t)by * 128 * DDd;
    } else {
        int row0 = by * 128;
        int b = row0 >> 10, t0 = row0 & 1023;
        Ag = (t0 < MMm) ? mem + ((size_t)b * MMm + t0) * DDd
                        : hc  + ((size_t)b * SSq + (t0 - MMm)) * DDd;
        if (z == 1) { B = Wk; C = k + (size_t)by * 128 * DDd; }
        else        { B = Wv; C = v + (size_t)by * 128 * DDd; }
    }
    const float* Bg = B + (size_t)blockIdx.x * 128;
    float* Cg = C + (size_t)blockIdx.x * 128;
    gemm_core<128, 4>(Ag, Bg, Cg, DDd, DDd, DDd, alpha, nullptr, 0);
}

// ======================================================================
// Flash fused attention (verified R4/R5 version, unchanged)
// ======================================================================
#define SMT   32
#define TN    64
#define QPITCH 68
#define WPITCH 100
#define SMEM_ATTN_FLOATS (2*SMT*QPITCH + 64*QPITCH + 96*QPITCH + SMT*WPITCH + SMT*QPITCH + 128 + 128 + 32 + 32)
#define SMEM_ATTN_BYTES  (SMEM_ATTN_FLOATS * 4)

__global__ void __launch_bounds__(256) fused_attn(
    const float* __restrict__ q, const float* __restrict__ k, const float* __restrict__ v,
    const float* __restrict__ r, const float* __restrict__ rwb, const float* __restrict__ rrb,
    float* __restrict__ attn)
{
    extern __shared__ float sm[];
    uint32_t* Qcb  = (uint32_t*)sm;
    uint32_t* Qrb  = Qcb + SMT * QPITCH;
    uint32_t* Ktb  = Qrb + SMT * QPITCH;
    uint32_t* Rwb  = Ktb + 64 * QPITCH;
    float* QRW     = (float*)(Rwb + 96 * QPITCH);
    uint32_t* Pt   = (uint32_t*)(QRW + SMT * WPITCH);
    float* partm   = (float*)(Pt + SMT * QPITCH);
    float* parts   = partm + 128;
    float* rowm    = parts + 128;
    float* rowsum  = rowm + 32;

    int tid = threadIdx.x, lane = tid & 31, warp = tid >> 5;
    int g = lane >> 2, tg = lane & 3;
    int s0 = blockIdx.x * SMT;
    int b = blockIdx.y >> 4, h = blockIdx.y & 15;

    const float* qb = q + (size_t)b * SSq * DDd + h * DKk;
    const float* kb = k + (size_t)b * TTt * DDd + h * DKk;
    const float* vb = v + (size_t)b * TTt * DDd + h * DKk;
    const float* rb = r + h * DKk;
    const float* wbv = rwb + h * DKk;
    const float* rbv = rrb + h * DKk;

#pragma unroll
    for (int j = 0; j < 2; j++) {
        int c = tid + j * 256;
        int row = c >> 4, k0 = (c & 15) * 4;
        float4 qv = *(const float4*)(qb + (size_t)(s0 + row) * DDd + k0);
        float4 w4 = *(const float4*)(wbv + k0);
        float4 r4 = *(const float4*)(rbv + k0);
        Qcb[row * QPITCH + k0 + 0] = f2tf32(qv.x + w4.x);
        Qcb[row * QPITCH + k0 + 1] = f2tf32(qv.y + w4.y);
        Qcb[row * QPITCH + k0 + 2] = f2tf32(qv.z + w4.z);
        Qcb[row * QPITCH + k0 + 3] = f2tf32(qv.w + w4.w);
        Qrb[row * QPITCH + k0 + 0] = f2tf32(qv.x + r4.x);
        Qrb[row * QPITCH + k0 + 1] = f2tf32(qv.y + r4.y);
        Qrb[row * QPITCH + k0 + 2] = f2tf32(qv.z + r4.z);
        Qrb[row * QPITCH + k0 + 3] = f2tf32(qv.w + r4.w);
    }
    if (tid < 32) { rowm[tid] = -1e30f; rowsum[tid] = 0.f; }

    int ntiles = (s0 + 543) / 64 + 1;
    int wm2 = (warp & 1) * 16;
    int wn2 = (warp >> 1) * 16;
    int wn3 = (warp >> 1) * 24;
    int wi  = warp >> 1;
    int r1 = wm2 + g, r2 = r1 + 8;

    float oacc[2][4];
#pragma unroll
    for (int nt = 0; nt < 2; nt++)
#pragma unroll
        for (int i = 0; i < 4; i++) oacc[nt][i] = 0.f;

    for (int it = 0; it < ntiles; it++) {
        int t0 = it * TN;
        int jb = t0 - s0 + 480;
        __syncthreads();

#pragma unroll
        for (int j = 0; j < 4; j++) {
            int c = tid + j * 256;
            int row = c >> 4, k0 = (c & 15) * 4;
            float4 kv4 = *(const float4*)(kb + (size_t)(t0 + row) * DDd + k0);
            Ktb[row * QPITCH + k0 + 0] = f2tf32(kv4.x);
            Ktb[row * QPITCH + k0 + 1] = f2tf32(kv4.y);
            Ktb[row * QPITCH + k0 + 2] = f2tf32(kv4.z);
            Ktb[row * QPITCH + k0 + 3] = f2tf32(kv4.w);
        }
#pragma unroll
        for (int j = 0; j < 6; j++) {
            int c = tid + j * 256;
            int row = c >> 4, k0 = (c & 15) * 4;
            int jg = jb + row; if (jg > TTt - 1) jg = TTt - 1;
            float4 rv4 = *(const float4*)(rb + (size_t)jg * DDd + k0);
            Rwb[row * QPITCH + k0 + 0] = f2tf32(rv4.x);
            Rwb[row * QPITCH + k0 + 1] = f2tf32(rv4.y);
            Rwb[row * QPITCH + k0 + 2] = f2tf32(rv4.z);
            Rwb[row * QPITCH + k0 + 3] = f2tf32(rv4.w);
        }
        __syncthreads();

        float ca[2][4], ra[3][4];
#pragma unroll
        for (int nt = 0; nt < 2; nt++)
#pragma unroll
            for (int i = 0; i < 4; i++) ca[nt][i] = 0.f;
#pragma unroll
        for (int nt = 0; nt < 3; nt++)
#pragma unroll
            for (int i = 0; i < 4; i++) ra[nt][i] = 0.f;

#pragma unroll
        for (int k8 = 0; k8 < 64; k8 += 8) {
            uint32_t af[4], afr[4];
            af[0]  = Qcb[(wm2 + g) * QPITCH + k8 + tg];
            af[1]  = Qcb[(wm2 + g + 8) * QPITCH + k8 + tg];
            af[2]  = Qcb[(wm2 + g) * QPITCH + k8 + tg + 4];
            af[3]  = Qcb[(wm2 + g + 8) * QPITCH + k8 + tg + 4];
            afr[0] = Qrb[(wm2 + g) * QPITCH + k8 + tg];
            afr[1] = Qrb[(wm2 + g + 8) * QPITCH + k8 + tg];
            afr[2] = Qrb[(wm2 + g) * QPITCH + k8 + tg + 4];
            afr[3] = Qrb[(wm2 + g + 8) * QPITCH + k8 + tg + 4];
#pragma unroll
            for (int nt = 0; nt < 2; nt++) {
                uint32_t bf[2];
                int col = wn2 + nt * 8 + g;
                bf[0] = Ktb[col * QPITCH + k8 + tg];
                bf[1] = Ktb[col * QPITCH + k8 + tg + 4];
                mma_tf32(ca[nt], af, bf);
            }
#pragma unroll
            for (int nt = 0; nt < 3; nt++) {
                uint32_t bf[2];
                int col = wn3 + nt * 8 + g;
                bf[0] = Rwb[col * QPITCH + k8 + tg];
                bf[1] = Rwb[col * QPITCH + k8 + tg + 4];
                mma_tf32(ra[nt], afr, bf);
            }
        }
#pragma unroll
        for (int nt = 0; nt < 3; nt++) {
            int c0 = wn3 + nt * 8 + tg * 2;
            QRW[r1 * WPITCH + c0]     = ra[nt][0];
            QRW[r1 * WPITCH + c0 + 1] = ra[nt][1];
            QRW[r2 * WPITCH + c0]     = ra[nt][2];
            QRW[r2 * WPITCH + c0 + 1] = ra[nt][3];
        }
        __syncthreads();

        float l[2][4];
#pragma unroll
        for (int nt = 0; nt < 2; nt++) {
            int tts = wn2 + nt * 8 + tg * 2;
#pragma unroll
            for (int i = 0; i < 4; i++) {
                int si = wm2 + g + ((i >= 2) ? 8 : 0);
                int tt = tts + (i & 1);
                int t = t0 + tt, s = s0 + si;
                l[nt][i] = (t - s <= MMm)
                    ? ca[nt][i] + QRW[si * WPITCH + tt + (SMT - 1) - si]
                    : -1e30f;
            }
        }
        float mx1 = fmaxf(fmaxf(l[0][0], l[0][1]), fmaxf(l[1][0], l[1][1]));
        float mx2 = fmaxf(fmaxf(l[0][2], l[0][3]), fmaxf(l[1][2], l[1][3]));
        mx1 = fmaxf(mx1, __shfl_xor_sync(0xffffffffu, mx1, 1));
        mx1 = fmaxf(mx1, __shfl_xor_sync(0xffffffffu, mx1, 2));
        mx2 = fmaxf(mx2, __shfl_xor_sync(0xffffffffu, mx2, 1));
        mx2 = fmaxf(mx2, __shfl_xor_sync(0xffffffffu, mx2, 2));
        if (tg == 0) { partm[r1 * 4 + wi] = mx1; partm[r2 * 4 + wi] = mx2; }

#pragma unroll
        for (int j = 0; j < 4; j++) {
            int c = tid + j * 256;
            int row = c >> 4, k0 = (c & 15) * 4;
            float4 vv4 = *(const float4*)(vb + (size_t)(t0 + row) * DDd + k0);
            Ktb[row * QPITCH + k0 + 0] = f2tf32(vv4.x);
            Ktb[row * QPITCH + k0 + 1] = f2tf32(vv4.y);
            Ktb[row * QPITCH + k0 + 2] = f2tf32(vv4.z);
            Ktb[row * QPITCH + k0 + 3] = f2tf32(vv4.w);
        }
        __syncthreads();

        float tm1 = fmaxf(fmaxf(partm[r1 * 4 + 0], partm[r1 * 4 + 1]),
                          fmaxf(partm[r1 * 4 + 2], partm[r1 * 4 + 3]));
        float tm2 = fmaxf(fmaxf(partm[r2 * 4 + 0], partm[r2 * 4 + 1]),
                          fmaxf(partm[r2 * 4 + 2], partm[r2 * 4 + 3]));
        float m1 = fmaxf(rowm[r1], tm1);
        float m2 = fmaxf(rowm[r2], tm2);
        float c1 = __expf(rowm[r1] - m1);
        float c2 = __expf(rowm[r2] - m2);
        float s1a = 0.f, s2a = 0.f;
#pragma unroll
        for (int nt = 0; nt < 2; nt++) {
            int tts = wn2 + nt * 8 + tg * 2;
            float p0 = __expf(l[nt][0] - m1);
            float p1 = __expf(l[nt][1] - m1);
            float p2 = __expf(l[nt][2] - m2);
            float p3 = __expf(l[nt][3] - m2);
            Pt[r1 * QPITCH + tts]     = f2tf32(p0);
            Pt[r1 * QPITCH + tts + 1] = f2tf32(p1);
            Pt[r2 * QPITCH + tts]     = f2tf32(p2);
            Pt[r2 * QPITCH + tts + 1] = f2tf32(p3);
            s1a += p0 + p1;
            s2a += p2 + p3;
        }
        s1a += __shfl_xor_sync(0xffffffffu, s1a, 1);
        s1a += __shfl_xor_sync(0xffffffffu, s1a, 2);
        s2a += __shfl_xor_sync(0xffffffffu, s2a, 1);
        s2a += __shfl_xor_sync(0xffffffffu, s2a, 2);
        if (tg == 0) { parts[r1 * 4 + wi] = s1a; parts[r2 * 4 + wi] = s2a; }
#pragma unroll
        for (int nt = 0; nt < 2; nt++) {
            oacc[nt][0] *= c1; oacc[nt][1] *= c1;
            oacc[nt][2] *= c2; oacc[nt][3] *= c2;
        }
        __syncthreads();

        if (wi == 0 && tg == 0) {
            rowsum[r1] = rowsum[r1] * c1 +
                parts[r1 * 4 + 0] + parts[r1 * 4 + 1] + parts[r1 * 4 + 2] + parts[r1 * 4 + 3];
            rowm[r1] = m1;
            rowsum[r2] = rowsum[r2] * c2 +
                parts[r2 * 4 + 0] + parts[r2 * 4 + 1] + parts[r2 * 4 + 2] + parts[r2 * 4 + 3];
            rowm[r2] = m2;
        }

#pragma unroll
        for (int k8 = 0; k8 < 64; k8 += 8) {
            uint32_t af[4];
            af[0] = Pt[r1 * QPITCH + k8 + tg];
            af[1] = Pt[r2 * QPITCH + k8 + tg];
            af[2] = Pt[r1 * QPITCH + k8 + tg + 4];
            af[3] = Pt[r2 * QPITCH + k8 + tg + 4];
#pragma unroll
            for (int nt = 0; nt < 2; nt++) {
                uint32_t bf[2];
                int col = wn2 + nt * 8 + g;
                bf[0] = Ktb[(k8 + tg) * QPITCH + col];
                bf[1] = Ktb[(k8 + tg + 4) * QPITCH + col];
                mma_tf32(oacc[nt], af, bf);
            }
        }
    }

    __syncthreads();
    float inv1 = 1.f / rowsum[r1];
    float inv2 = 1.f / rowsum[r2];
    float* ob = attn + ((size_t)b * SSq + s0) * DDd + h * DKk;
#pragma unroll
    for (int nt = 0; nt < 2; nt++) {
        int c0 = wn2 + nt * 8 + tg * 2;
        *(float2*)(ob + (size_t)r1 * DDd + c0) =
            make_float2(oacc[nt][0] * inv1, oacc[nt][1] * inv1);
        *(float2*)(ob + (size_t)r2 * DDd + c0) =
            make_float2(oacc[nt][2] * inv2, oacc[nt][3] * inv2);
    }
}

// ---------------- residual + LayerNorm over (x0 + x1 + res) ----------------
__global__ void ln_kernel2(const float* __restrict__ x0, const float* __restrict__ x1,
                           const float* __restrict__ res,
                           const float* __restrict__ g, const float* __restrict__ b,
                           float* __restrict__ out)
{
    int row = blockIdx.x;
    const float* xr0 = x0 + (size_t)row * DDd;
    const float* xr1 = x1 + (size_t)row * DDd;
    const float* rr  = res + (size_t)row * DDd;
    __shared__ float redA[33], redB[33];
    int tid = threadIdx.x;

    float loc[4];
    float s1 = 0.f, s2 = 0.f;
#pragma unroll
    for (int i = 0; i < 4; i++) {
        int d = tid + i * 256;
        float v = xr0[d] + xr1[d] + rr[d];
        loc[i] = v;
        s1 += v;
        s2 += v * v;
    }
#pragma unroll
    for (int o = 16; o; o >>= 1) {
        s1 += __shfl_xor_sync(0xffffffffu, s1, o);
        s2 += __shfl_xor_sync(0xffffffffu, s2, o);
    }
    if ((tid & 31) == 0) { redA[tid >> 5] = s1; redB[tid >> 5] = s2; }
    __syncthreads();
    if (tid < 32) {
        float a = (tid < 8) ? redA[tid] : 0.f;
        float c = (tid < 8) ? redB[tid] : 0.f;
#pragma unroll
        for (int o = 4; o; o >>= 1) {
            a += __shfl_xor_sync(0xffffffffu, a, o);
            c += __shfl_xor_sync(0xffffffffu, c, o);
        }
        if (tid == 0) { redA[32] = a; redB[32] = c; }
    }
    __syncthreads();
    float mu  = redA[32] * (1.f / DDd);
    float var = redB[32] * (1.f / DDd) - mu * mu;
    float rstd = rsqrtf(var + 1e-5f);
#pragma unroll
    for (int i = 0; i < 4; i++) {
        int d = tid + i * 256;
        out[(size_t)row * DDd + d] = (loc[i] - mu) * rstd * g[d] + b[d];
    }
}

// ---------------- host-side orchestration ----------------
extern "C" void kernel_launch(void* const* d_in, const int* in_sizes, int n_in,
                              void* d_out, int out_size)
{
    const float* x      = (const float*)d_in[0];
    const float* memory = (const float*)d_in[1];
    const float* Wq  = (const float*)d_in[2];
    const float* Wk  = (const float*)d_in[3];
    const float* Wv  = (const float*)d_in[4];
    const float* Wr  = (const float*)d_in[5];
    const float* Wo  = (const float*)d_in[6];
    const float* rwb = (const float*)d_in[7];
    const float* rrb = (const float*)d_in[8];
    const float* ln1g = (const float*)d_in[9];
    const float* ln1b = (const float*)d_in[10];
    const float* ln2g = (const float*)d_in[11];
    const float* ln2b = (const float*)d_in[12];
    const float* W1  = (const float*)d_in[13];
    const float* b1  = (const float*)d_in[14];
    const float* W2  = (const float*)d_in[15];
    const float* b2  = (const float*)d_in[16];
    float* out = (float*)d_out;

    float *pos, *q, *k, *v, *r, *attn, *tmp, *tmp2, *ff, *h, *h1;
    cudaGetSymbolAddress((void**)&pos,  g_pos);
    cudaGetSymbolAddress((void**)&q,    g_q);
    cudaGetSymbolAddress((void**)&k,    g_k);
    cudaGetSymbolAddress((void**)&v,    g_v);
    cudaGetSymbolAddress((void**)&r,    g_r);
    cudaGetSymbolAddress((void**)&attn, g_attn);
    cudaGetSymbolAddress((void**)&tmp,  g_tmp);
    cudaGetSymbolAddress((void**)&tmp2, g_tmp2);
    cudaGetSymbolAddress((void**)&ff,   g_ff);
    cudaGetSymbolAddress((void**)&h,    g_h);
    cudaGetSymbolAddress((void**)&h1,   g_h1);

    cudaFuncSetAttribute(fused_attn, cudaFuncAttributeMaxDynamicSharedMemorySize,
                         SMEM_ATTN_BYTES);

    pos_kernel<<<(TTt * (DDd / 2) + 255) / 256, 256>>>(pos);

    const float* hcur = x;
    for (int l = 0; l < LL; l++) {
        // q/k/v/r grouped, 128x128 tiles, concat folded into A-pointer
        dim3 gG(DDd / 128, (BB * TTt) / 128, 4);   // (8, 16, 4), 384 working CTAs
        grouped_qkvr<<<gG, 256>>>(hcur, memory + (size_t)l * BB * MMm * DDd, pos,
                                  Wq + (size_t)l * DDd * DDd, Wk + (size_t)l * DDd * DDd,
                                  Wv + (size_t)l * DDd * DDd, Wr + (size_t)l * DDd * DDd,
                                  q, k, v, r);

        // flash fused attention
        dim3 gA(SSq / SMT, BB * HHh);
        fused_attn<<<gA, 256, SMEM_ATTN_BYTES>>>(
            q, k, v, r, rwb + (size_t)l * HHh * DKk, rrb + (size_t)l * HHh * DKk, attn);

        // output projection: split-K=2, BM=64/BN=128 -> 256 CTAs
        dim3 gO(DDd / 128, (BB * SSq) / 64, 2);
        tc_gemm_splitk<64, 4><<<gO, 256>>>(attn, Wo + (size_t)l * DDd * DDd,
                                           tmp, tmp2, DDd, DDd, nullptr);
        ln_kernel2<<<BB * SSq, 256>>>(tmp, tmp2, hcur,
                                      ln1g + l * DDd, ln1b + l * DDd, h1);

        // FFN
        dim3 gF1(FFf / 128, (BB * SSq) / 128);     // 256 CTAs
        tc_gemm_k<128, 4><<<gF1, 256>>>(h1, W1 + (size_t)l * DDd * FFf, ff,
                                        FFf, DDd, 1.f, b1 + l * FFf, 1);
        // ff2: split-K=2 -> 256 CTAs, K=2048 each
        dim3 gF2(DDd / 128, (BB * SSq) / 64, 2);
        tc_gemm_splitk<64, 4><<<gF2, 256>>>(ff, W2 + (size_t)l * FFf * DDd,
                                            tmp, tmp2, DDd, FFf, b2 + l * DDd);

        float* hout = (l == LL - 1) ? out : h;
        ln_kernel2<<<BB * SSq, 256>>>(tmp, tmp2, h1,
                                      ln2g + l * DDd, ln2b + l * DDd, hout);
        hcur = h;
    }
}

// round 8
// speedup vs baseline: 1.4694x; 1.0302x over previous
#include <cuda_runtime.h>
#include <math.h>
#include <stdint.h>

// Problem dims
#define LL  4
#define BB  2
#define SSq 512
#define MMm 512
#define DDd 1024
#define HHh 16
#define DKk 64
#define FFf 4096
#define TTt (SSq + MMm)   // 1024

// ---------------- scratch ----------------
__device__ float g_pos[TTt * DDd];
__device__ float g_q  [BB * SSq * DDd];
__device__ float g_k  [BB * TTt * DDd];   // tf32 bits
__device__ float g_v  [BB * TTt * DDd];   // tf32 bits
__device__ float g_r  [TTt * DDd];        // tf32 bits
__device__ float g_attn[BB * SSq * DDd];
__device__ float g_tmp [BB * SSq * DDd];
__device__ float g_tmp2[BB * SSq * DDd];
__device__ float g_ff  [BB * SSq * FFf];
__device__ float g_h   [BB * SSq * DDd];
__device__ float g_h1  [BB * SSq * DDd];

// ---------------- PTX helpers ----------------
__device__ __forceinline__ uint32_t f2tf32(float f) {
    uint32_t u;
    asm("cvt.rna.tf32.f32 %0, %1;" : "=r"(u) : "f"(f));
    return u;
}
__device__ __forceinline__ void mma_tf32(float c[4], const uint32_t a[4], const uint32_t b[2]) {
    asm volatile(
        "mma.sync.aligned.m16n8k8.row.col.f32.tf32.tf32.f32 "
        "{%0,%1,%2,%3},{%4,%5,%6,%7},{%8,%9},{%0,%1,%2,%3};"
        : "+f"(c[0]), "+f"(c[1]), "+f"(c[2]), "+f"(c[3])
        : "r"(a[0]), "r"(a[1]), "r"(a[2]), "r"(a[3]), "r"(b[0]), "r"(b[1]));
}
__device__ __forceinline__ void cp_async16(void* smem, const void* g) {
    uint32_t s = (uint32_t)__cvta_generic_to_shared(smem);
    asm volatile("cp.async.cg.shared.global [%0], [%1], 16;" :: "r"(s), "l"(g));
}
#define CP_COMMIT() asm volatile("cp.async.commit_group;")
#define CP_WAIT(n)  asm volatile("cp.async.wait_group %0;" :: "n"(n))

// ---------------- positional encodings (sin+cos per thread) ----------------
__global__ void pos_kernel(float* __restrict__ pos)
{
    int idx = blockIdx.x * blockDim.x + threadIdx.x;
    if (idx >= TTt * (DDd / 2)) return;
    int t = idx / (DDd / 2), j = idx % (DDd / 2);
    double invf = exp(((double)(-2 * j) / (double)DDd) * 9.210340371976184);
    double ang  = (double)(TTt - 1 - t) * invf;
    double kk   = floor(ang * 0.15915494309189535);
    float a = (float)(ang - kk * 6.283185307179586);
    pos[(size_t)t * DDd + j]            = sinf(a);
    pos[(size_t)t * DDd + j + DDd / 2]  = cosf(a);
}

// ======================================================================
// GEMM core: Cg = alpha*Ag@Bg (+bias)(+relu)(optional tf32 output).
// Pointers PRE-OFFSET. BM x (NWN*32), BK=16, 256 threads.
// ======================================================================
template<int BM, int NWN>
__device__ __forceinline__ void gemm_core(
    const float* __restrict__ Ag, const float* __restrict__ Bg, float* __restrict__ Cg,
    int N, int K, int lda, float alpha, const float* __restrict__ biasg, int relu,
    int cvt_out)
{
    constexpr int BN = NWN * 32;
    constexpr int NWM = 8 / NWN;
    constexpr int WM = BM / NWM;
    constexpr int MT = WM / 16;
    constexpr int BPITCH = BN + 8;
    constexpr int NA_CH = BM / 64;
    constexpr int NB_CH = BN / 64;

    __shared__ uint32_t As[2][BM][20];
    __shared__ uint32_t Bs[2][16][BPITCH];

    int tid = threadIdx.x, lane = tid & 31, warp = tid >> 5;
    int g = lane >> 2, tg = lane & 3;
    int warp_m = warp % NWM, warp_n = warp / NWM;
    int wm = warp_m * WM, wn = warp_n * 32;

    float acc[MT][4][4];
#pragma unroll
    for (int mt = 0; mt < MT; mt++)
#pragma unroll
        for (int nt = 0; nt < 4; nt++)
#pragma unroll
            for (int i = 0; i < 4; i++) acc[mt][nt][i] = 0.f;

    int ar[NA_CH], ak[NA_CH];
#pragma unroll
    for (int j = 0; j < NA_CH; j++) {
        int c = tid + j * 256;
        ar[j] = c >> 2; ak[j] = (c & 3) * 4;
    }
    int bk[NB_CH], bn[NB_CH];
#pragma unroll
    for (int j = 0; j < NB_CH; j++) {
        int c = tid + j * 256;
        if (BN == 128) { bk[j] = c >> 5; bn[j] = (c & 31) * 4; }
        else           { bk[j] = c >> 4; bn[j] = (c & 15) * 4; }
    }

    int nk = K / 16;
    float4 sA[NA_CH], sB[NB_CH];

#pragma unroll
    for (int j = 0; j < NA_CH; j++)
        sA[j] = *(const float4*)(Ag + (size_t)ar[j] * lda + ak[j]);
#pragma unroll
    for (int j = 0; j < NB_CH; j++)
        sB[j] = *(const float4*)(Bg + (size_t)bk[j] * N + bn[j]);
#pragma unroll
    for (int j = 0; j < NA_CH; j++) {
        uint4 u = make_uint4(f2tf32(sA[j].x), f2tf32(sA[j].y), f2tf32(sA[j].z), f2tf32(sA[j].w));
        *(uint4*)&As[0][ar[j]][ak[j]] = u;
    }
#pragma unroll
    for (int j = 0; j < NB_CH; j++) {
        uint4 u = make_uint4(f2tf32(sB[j].x), f2tf32(sB[j].y), f2tf32(sB[j].z), f2tf32(sB[j].w));
        *(uint4*)&Bs[0][bk[j]][bn[j]] = u;
    }
    __syncthreads();

    for (int kt = 0; kt < nk; kt++) {
        int buf = kt & 1;
        bool more = (kt + 1 < nk);
        if (more) {
#pragma unroll
            for (int j = 0; j < NA_CH; j++)
                sA[j] = *(const float4*)(Ag + (size_t)ar[j] * lda + (kt + 1) * 16 + ak[j]);
#pragma unroll
            for (int j = 0; j < NB_CH; j++)
                sB[j] = *(const float4*)(Bg + (size_t)((kt + 1) * 16 + bk[j]) * N + bn[j]);
        }

#pragma unroll
        for (int ks = 0; ks < 2; ks++) {
            uint32_t af[MT][4], bf[4][2];
#pragma unroll
            for (int mt = 0; mt < MT; mt++) {
                int row = wm + mt * 16;
                af[mt][0] = As[buf][row + g][ks * 8 + tg];
                af[mt][1] = As[buf][row + g + 8][ks * 8 + tg];
                af[mt][2] = As[buf][row + g][ks * 8 + tg + 4];
                af[mt][3] = As[buf][row + g + 8][ks * 8 + tg + 4];
            }
#pragma unroll
            for (int nt = 0; nt < 4; nt++) {
                int col = wn + nt * 8 + g;
                bf[nt][0] = Bs[buf][ks * 8 + tg][col];
                bf[nt][1] = Bs[buf][ks * 8 + tg + 4][col];
            }
#pragma unroll
            for (int mt = 0; mt < MT; mt++)
#pragma unroll
                for (int nt = 0; nt < 4; nt++) mma_tf32(acc[mt][nt], af[mt], bf[nt]);
        }

        if (more) {
            int nb = buf ^ 1;
#pragma unroll
            for (int j = 0; j < NA_CH; j++) {
                uint4 u = make_uint4(f2tf32(sA[j].x), f2tf32(sA[j].y), f2tf32(sA[j].z), f2tf32(sA[j].w));
                *(uint4*)&As[nb][ar[j]][ak[j]] = u;
            }
#pragma unroll
            for (int j = 0; j < NB_CH; j++) {
                uint4 u = make_uint4(f2tf32(sB[j].x), f2tf32(sB[j].y), f2tf32(sB[j].z), f2tf32(sB[j].w));
                *(uint4*)&Bs[nb][bk[j]][bn[j]] = u;
            }
            __syncthreads();
        }
    }

#pragma unroll
    for (int mt = 0; mt < MT; mt++) {
#pragma unroll
        for (int nt = 0; nt < 4; nt++) {
            int row = wm + mt * 16 + g;
            int col = wn + nt * 8 + tg * 2;
            float bx0 = 0.f, bx1 = 0.f;
            if (biasg) { bx0 = biasg[col]; bx1 = biasg[col + 1]; }
            float v0 = acc[mt][nt][0] * alpha + bx0;
            float v1 = acc[mt][nt][1] * alpha + bx1;
            float v2 = acc[mt][nt][2] * alpha + bx0;
            float v3 = acc[mt][nt][3] * alpha + bx1;
            if (relu) {
                v0 = fmaxf(v0, 0.f); v1 = fmaxf(v1, 0.f);
                v2 = fmaxf(v2, 0.f); v3 = fmaxf(v3, 0.f);
            }
            if (cvt_out) {
                v0 = __uint_as_float(f2tf32(v0));
                v1 = __uint_as_float(f2tf32(v1));
                v2 = __uint_as_float(f2tf32(v2));
                v3 = __uint_as_float(f2tf32(v3));
            }
            *(float2*)(Cg + (size_t)row * N + col)       = make_float2(v0, v1);
            *(float2*)(Cg + (size_t)(row + 8) * N + col) = make_float2(v2, v3);
        }
    }
}

template<int BM, int NWN>
__global__ void __launch_bounds__(256) tc_gemm_k(
    const float* __restrict__ A, const float* __restrict__ B, float* __restrict__ C,
    int N, int K, float alpha, const float* __restrict__ bias, int relu)
{
    constexpr int BN = NWN * 32;
    const float* Ag = A + (size_t)blockIdx.y * BM * K;
    const float* Bg = B + (size_t)blockIdx.x * BN;
    float* Cg = C + (size_t)blockIdx.y * BM * N + (size_t)blockIdx.x * BN;
    const float* bg = bias ? bias + (size_t)blockIdx.x * BN : nullptr;
    gemm_core<BM, NWN>(Ag, Bg, Cg, N, K, K, alpha, bg, relu, 0);
}

// split-K=2 GEMM: z-half writes C0 (z=0) or C1 (z=1); bias only in z=0.
template<int BM, int NWN>
__global__ void __launch_bounds__(256) tc_gemm_splitk(
    const float* __restrict__ A, const float* __restrict__ B,
    float* __restrict__ C0, float* __restrict__ C1,
    int N, int K, const float* __restrict__ bias)
{
    constexpr int BN = NWN * 32;
    int z = blockIdx.z;
    int K2 = K >> 1;
    const float* Ag = A + (size_t)blockIdx.y * BM * K + (size_t)z * K2;
    const float* Bg = B + (size_t)z * K2 * N + (size_t)blockIdx.x * BN;
    float* C = z ? C1 : C0;
    float* Cg = C + (size_t)blockIdx.y * BM * N + (size_t)blockIdx.x * BN;
    const float* bg = (bias && z == 0) ? bias + (size_t)blockIdx.x * BN : nullptr;
    gemm_core<BM, NWN>(Ag, Bg, Cg, N, K2, K, 1.f, bg, 0, 0);
}

// grouped q/k/v/r projections. Compacted grid (8, 48): y<8 q, [8,24) k,
// [24,40) v, [40,48) r. concat folded into A pointer; k/v/r emitted as tf32.
__global__ void __launch_bounds__(256) grouped_qkvr(
    const float* __restrict__ hc, const float* __restrict__ mem, const float* __restrict__ pos,
    const float* __restrict__ Wq, const float* __restrict__ Wk,
    const float* __restrict__ Wv, const float* __restrict__ Wr,
    float* __restrict__ q, float* __restrict__ k, float* __restrict__ v, float* __restrict__ r)
{
    int y = blockIdx.y;
    const float* Ag; const float* B; float* C; float alpha = 1.f; int cvt = 1;
    if (y < 8) {
        Ag = hc + (size_t)y * 128 * DDd; B = Wq; C = q + (size_t)y * 128 * DDd;
        alpha = 0.125f; cvt = 0;
    } else if (y < 40) {
        int yy = (y < 24) ? y - 8 : y - 24;
        int row0 = yy * 128;
        int b = row0 >> 10, t0 = row0 & 1023;
        Ag = (t0 < MMm) ? mem + ((size_t)b * MMm + t0) * DDd
                        : hc  + ((size_t)b * SSq + (t0 - MMm)) * DDd;
        if (y < 24) { B = Wk; C = k + (size_t)yy * 128 * DDd; }
        else        { B = Wv; C = v + (size_t)yy * 128 * DDd; }
    } else {
        int yy = y - 40;
        Ag = pos + (size_t)yy * 128 * DDd; B = Wr; C = r + (size_t)yy * 128 * DDd;
    }
    const float* Bg = B + (size_t)blockIdx.x * 128;
    float* Cg = C + (size_t)blockIdx.x * 128;
    gemm_core<128, 4>(Ag, Bg, Cg, DDd, DDd, DDd, alpha, nullptr, 0, cvt);
}

// ======================================================================
// Flash fused attention with cp.async pipelining. k/v/r arrive as tf32
// bits -> raw async copies, no per-tile conversion. 2 CTAs/SM.
// ======================================================================
#define SMT   32
#define TN    64
#define QPITCH 68
#define WPITCH 100
// floats: Qc 32*68, Qr 32*68, K 64*68, R 96*68, V 64*68, QRW 32*100,
//         Pt 32*68, partm 128, parts 128, rowm 32, rowsum 32
#define SMEM_ATTN_FLOATS (2*SMT*QPITCH + 64*QPITCH + 96*QPITCH + 64*QPITCH + SMT*WPITCH + SMT*QPITCH + 128 + 128 + 32 + 32)
#define SMEM_ATTN_BYTES  (SMEM_ATTN_FLOATS * 4)

__global__ void __launch_bounds__(256) fused_attn(
    const float* __restrict__ q, const float* __restrict__ k, const float* __restrict__ v,
    const float* __restrict__ r, const float* __restrict__ rwb, const float* __restrict__ rrb,
    float* __restrict__ attn)
{
    extern __shared__ float sm[];
    uint32_t* Qcb  = (uint32_t*)sm;                       // [32][68]
    uint32_t* Qrb  = Qcb + SMT * QPITCH;                  // [32][68]
    uint32_t* Ktb  = Qrb + SMT * QPITCH;                  // [64][68]
    uint32_t* Rwb  = Ktb + 64 * QPITCH;                   // [96][68]
    uint32_t* Vtb  = Rwb + 96 * QPITCH;                   // [64][68]
    float* QRW     = (float*)(Vtb + 64 * QPITCH);         // [32][100]
    uint32_t* Pt   = (uint32_t*)(QRW + SMT * WPITCH);     // [32][68]
    float* partm   = (float*)(Pt + SMT * QPITCH);         // [32][4]
    float* parts   = partm + 128;
    float* rowm    = parts + 128;
    float* rowsum  = rowm + 32;

    int tid = threadIdx.x, lane = tid & 31, warp = tid >> 5;
    int g = lane >> 2, tg = lane & 3;
    int s0 = (15 - blockIdx.x) * SMT;     // heavy blocks first
    int b = blockIdx.y >> 4, h = blockIdx.y & 15;

    const float* qb = q + (size_t)b * SSq * DDd + h * DKk;
    const float* kb = k + (size_t)b * TTt * DDd + h * DKk;
    const float* vb = v + (size_t)b * TTt * DDd + h * DKk;
    const float* rb = r + h * DKk;
    const float* wbv = rwb + h * DKk;
    const float* rbv = rrb + h * DKk;

    int ntiles = (s0 + 543) / 64 + 1;

    // loader index maps (16B chunks)
    int lrow = tid >> 4, lk0 = (tid & 15) * 4;

    auto issue_KR = [&](int it) {
        if (it < ntiles) {
            int t0 = it * TN, jb = t0 - s0 + 480;
#pragma unroll
            for (int j = 0; j < 4; j++) {
                int row = lrow + j * 16;
                cp_async16(&Ktb[row * QPITCH + lk0], kb + (size_t)(t0 + row) * DDd + lk0);
            }
#pragma unroll
            for (int j = 0; j < 6; j++) {
                int row = lrow + j * 16;
                int jg = jb + row; if (jg > TTt - 1) jg = TTt - 1;
                cp_async16(&Rwb[row * QPITCH + lk0], rb + (size_t)jg * DDd + lk0);
            }
        }
        CP_COMMIT();
    };
    auto issue_V = [&](int it) {
        if (it < ntiles) {
            int t0 = it * TN;
#pragma unroll
            for (int j = 0; j < 4; j++) {
                int row = lrow + j * 16;
                cp_async16(&Vtb[row * QPITCH + lk0], vb + (size_t)(t0 + row) * DDd + lk0);
            }
        }
        CP_COMMIT();
    };

    issue_KR(0);
    issue_V(0);

    // phase 1: Qc = q + rwb, Qr = q + rrb (tf32) while tile-0 loads fly
#pragma unroll
    for (int j = 0; j < 2; j++) {
        int c = tid + j * 256;
        int row = c >> 4, k0 = (c & 15) * 4;
        float4 qv = *(const float4*)(qb + (size_t)(s0 + row) * DDd + k0);
        float4 w4 = *(const float4*)(wbv + k0);
        float4 r4 = *(const float4*)(rbv + k0);
        Qcb[row * QPITCH + k0 + 0] = f2tf32(qv.x + w4.x);
        Qcb[row * QPITCH + k0 + 1] = f2tf32(qv.y + w4.y);
        Qcb[row * QPITCH + k0 + 2] = f2tf32(qv.z + w4.z);
        Qcb[row * QPITCH + k0 + 3] = f2tf32(qv.w + w4.w);
        Qrb[row * QPITCH + k0 + 0] = f2tf32(qv.x + r4.x);
        Qrb[row * QPITCH + k0 + 1] = f2tf32(qv.y + r4.y);
        Qrb[row * QPITCH + k0 + 2] = f2tf32(qv.z + r4.z);
        Qrb[row * QPITCH + k0 + 3] = f2tf32(qv.w + r4.w);
    }
    if (tid < 32) { rowm[tid] = -1e30f; rowsum[tid] = 0.f; }

    int wm2 = (warp & 1) * 16;
    int wn2 = (warp >> 1) * 16;
    int wn3 = (warp >> 1) * 24;
    int wi  = warp >> 1;
    int r1 = wm2 + g, r2 = r1 + 8;

    float oacc[2][4];
#pragma unroll
    for (int nt = 0; nt < 2; nt++)
#pragma unroll
        for (int i = 0; i < 4; i++) oacc[nt][i] = 0.f;

    for (int it = 0; it < ntiles; it++) {
        int t0 = it * TN;
        CP_WAIT(1);          // K/R(it) landed (V group may still fly)
        __syncthreads();

        // QK content + rel MMAs
        float ca[2][4], ra[3][4];
#pragma unroll
        for (int nt = 0; nt < 2; nt++)
#pragma unroll
            for (int i = 0; i < 4; i++) ca[nt][i] = 0.f;
#pragma unroll
        for (int nt = 0; nt < 3; nt++)
#pragma unroll
            for (int i = 0; i < 4; i++) ra[nt][i] = 0.f;

#pragma unroll
        for (int k8 = 0; k8 < 64; k8 += 8) {
            uint32_t af[4], afr[4];
            af[0]  = Qcb[(wm2 + g) * QPITCH + k8 + tg];
            af[1]  = Qcb[(wm2 + g + 8) * QPITCH + k8 + tg];
            af[2]  = Qcb[(wm2 + g) * QPITCH + k8 + tg + 4];
            af[3]  = Qcb[(wm2 + g + 8) * QPITCH + k8 + tg + 4];
            afr[0] = Qrb[(wm2 + g) * QPITCH + k8 + tg];
            afr[1] = Qrb[(wm2 + g + 8) * QPITCH + k8 + tg];
            afr[2] = Qrb[(wm2 + g) * QPITCH + k8 + tg + 4];
            afr[3] = Qrb[(wm2 + g + 8) * QPITCH + k8 + tg + 4];
#pragma unroll
            for (int nt = 0; nt < 2; nt++) {
                uint32_t bf[2];
                int col = wn2 + nt * 8 + g;
                bf[0] = Ktb[col * QPITCH + k8 + tg];
                bf[1] = Ktb[col * QPITCH + k8 + tg + 4];
                mma_tf32(ca[nt], af, bf);
            }
#pragma unroll
            for (int nt = 0; nt < 3; nt++) {
                uint32_t bf[2];
                int col = wn3 + nt * 8 + g;
                bf[0] = Rwb[col * QPITCH + k8 + tg];
                bf[1] = Rwb[col * QPITCH + k8 + tg + 4];
                mma_tf32(ra[nt], afr, bf);
            }
        }
#pragma unroll
        for (int nt = 0; nt < 3; nt++) {
            int c0 = wn3 + nt * 8 + tg * 2;
            QRW[r1 * WPITCH + c0]     = ra[nt][0];
            QRW[r1 * WPITCH + c0 + 1] = ra[nt][1];
            QRW[r2 * WPITCH + c0]     = ra[nt][2];
            QRW[r2 * WPITCH + c0 + 1] = ra[nt][3];
        }
        __syncthreads();   // sync2: QRW ready, K/R reads done

        issue_KR(it + 1);  // prefetch next K/R into now-free buffers

        // combine -> logits; tile row max
        float l[2][4];
#pragma unroll
        for (int nt = 0; nt < 2; nt++) {
            int tts = wn2 + nt * 8 + tg * 2;
#pragma unroll
            for (int i = 0; i < 4; i++) {
                int si = wm2 + g + ((i >= 2) ? 8 : 0);
                int tt = tts + (i & 1);
                int t = t0 + tt, s = s0 + si;
                l[nt][i] = (t - s <= MMm)
                    ? ca[nt][i] + QRW[si * WPITCH + tt + (SMT - 1) - si]
                    : -1e30f;
            }
        }
        float mx1 = fmaxf(fmaxf(l[0][0], l[0][1]), fmaxf(l[1][0], l[1][1]));
        float mx2 = fmaxf(fmaxf(l[0][2], l[0][3]), fmaxf(l[1][2], l[1][3]));
        mx1 = fmaxf(mx1, __shfl_xor_sync(0xffffffffu, mx1, 1));
        mx1 = fmaxf(mx1, __shfl_xor_sync(0xffffffffu, mx1, 2));
        mx2 = fmaxf(mx2, __shfl_xor_sync(0xffffffffu, mx2, 1));
        mx2 = fmaxf(mx2, __shfl_xor_sync(0xffffffffu, mx2, 2));
        if (tg == 0) { partm[r1 * 4 + wi] = mx1; partm[r2 * 4 + wi] = mx2; }

        CP_WAIT(1);        // V(it) landed (leaves KR(it+1) in flight)
        __syncthreads();   // sync3: partm + V visible

        float tm1 = fmaxf(fmaxf(partm[r1 * 4 + 0], partm[r1 * 4 + 1]),
                          fmaxf(partm[r1 * 4 + 2], partm[r1 * 4 + 3]));
        float tm2 = fmaxf(fmaxf(partm[r2 * 4 + 0], partm[r2 * 4 + 1]),
                          fmaxf(partm[r2 * 4 + 2], partm[r2 * 4 + 3]));
        float m1 = fmaxf(rowm[r1], tm1);
        float m2 = fmaxf(rowm[r2], tm2);
        float c1 = __expf(rowm[r1] - m1);
        float c2 = __expf(rowm[r2] - m2);
        float s1a = 0.f, s2a = 0.f;
#pragma unroll
        for (int nt = 0; nt < 2; nt++) {
            int tts = wn2 + nt * 8 + tg * 2;
            float p0 = __expf(l[nt][0] - m1);
            float p1 = __expf(l[nt][1] - m1);
            float p2 = __expf(l[nt][2] - m2);
            float p3 = __expf(l[nt][3] - m2);
            Pt[r1 * QPITCH + tts]     = f2tf32(p0);
            Pt[r1 * QPITCH + tts + 1] = f2tf32(p1);
            Pt[r2 * QPITCH + tts]     = f2tf32(p2);
            Pt[r2 * QPITCH + tts + 1] = f2tf32(p3);
            s1a += p0 + p1;
            s2a += p2 + p3;
        }
        s1a += __shfl_xor_sync(0xffffffffu, s1a, 1);
        s1a += __shfl_xor_sync(0xffffffffu, s1a, 2);
        s2a += __shfl_xor_sync(0xffffffffu, s2a, 1);
        s2a += __shfl_xor_sync(0xffffffffu, s2a, 2);
        if (tg == 0) { parts[r1 * 4 + wi] = s1a; parts[r2 * 4 + wi] = s2a; }
#pragma unroll
        for (int nt = 0; nt < 2; nt++) {
            oacc[nt][0] *= c1; oacc[nt][1] *= c1;
            oacc[nt][2] *= c2; oacc[nt][3] *= c2;
        }
        __syncthreads();   // sync4: Pt + parts visible

        if (wi == 0 && tg == 0) {
            rowsum[r1] = rowsum[r1] * c1 +
                parts[r1 * 4 + 0] + parts[r1 * 4 + 1] + parts[r1 * 4 + 2] + parts[r1 * 4 + 3];
            rowm[r1] = m1;
            rowsum[r2] = rowsum[r2] * c2 +
                parts[r2 * 4 + 0] + parts[r2 * 4 + 1] + parts[r2 * 4 + 2] + parts[r2 * 4 + 3];
            rowm[r2] = m2;
        }

        // P @ V accumulate
#pragma unroll
        for (int k8 = 0; k8 < 64; k8 += 8) {
            uint32_t af[4];
            af[0] = Pt[r1 * QPITCH + k8 + tg];
            af[1] = Pt[r2 * QPITCH + k8 + tg];
            af[2] = Pt[r1 * QPITCH + k8 + tg + 4];
            af[3] = Pt[r2 * QPITCH + k8 + tg + 4];
#pragma unroll
            for (int nt = 0; nt < 2; nt++) {
                uint32_t bf[2];
                int col = wn2 + nt * 8 + g;
                bf[0] = Vtb[(k8 + tg) * QPITCH + col];
                bf[1] = Vtb[(k8 + tg + 4) * QPITCH + col];
                mma_tf32(oacc[nt], af, bf);
            }
        }
        __syncthreads();   // all V reads done before refill
        issue_V(it + 1);
    }

    __syncthreads();
    float inv1 = 1.f / rowsum[r1];
    float inv2 = 1.f / rowsum[r2];
    float* ob = attn + ((size_t)b * SSq + s0) * DDd + h * DKk;
#pragma unroll
    for (int nt = 0; nt < 2; nt++) {
        int c0 = wn2 + nt * 8 + tg * 2;
        *(float2*)(ob + (size_t)r1 * DDd + c0) =
            make_float2(oacc[nt][0] * inv1, oacc[nt][1] * inv1);
        *(float2*)(ob + (size_t)r2 * DDd + c0) =
            make_float2(oacc[nt][2] * inv2, oacc[nt][3] * inv2);
    }
}

// ---------------- residual + LayerNorm over (x0 + x1 + res) ----------------
__global__ void ln_kernel2(const float* __restrict__ x0, const float* __restrict__ x1,
                           const float* __restrict__ res,
                           const float* __restrict__ g, const float* __restrict__ b,
                           float* __restrict__ out)
{
    int row = blockIdx.x;
    const float* xr0 = x0 + (size_t)row * DDd;
    const float* xr1 = x1 + (size_t)row * DDd;
    const float* rr  = res + (size_t)row * DDd;
    __shared__ float redA[33], redB[33];
    int tid = threadIdx.x;

    float loc[4];
    float s1 = 0.f, s2 = 0.f;
#pragma unroll
    for (int i = 0; i < 4; i++) {
        int d = tid + i * 256;
        float v = xr0[d] + xr1[d] + rr[d];
        loc[i] = v;
        s1 += v;
        s2 += v * v;
    }
#pragma unroll
    for (int o = 16; o; o >>= 1) {
        s1 += __shfl_xor_sync(0xffffffffu, s1, o);
        s2 += __shfl_xor_sync(0xffffffffu, s2, o);
    }
    if ((tid & 31) == 0) { redA[tid >> 5] = s1; redB[tid >> 5] = s2; }
    __syncthreads();
    if (tid < 32) {
        float a = (tid < 8) ? redA[tid] : 0.f;
        float c = (tid < 8) ? redB[tid] : 0.f;
#pragma unroll
        for (int o = 4; o; o >>= 1) {
            a += __shfl_xor_sync(0xffffffffu, a, o);
            c += __shfl_xor_sync(0xffffffffu, c, o);
        }
        if (tid == 0) { redA[32] = a; redB[32] = c; }
    }
    __syncthreads();
    float mu  = redA[32] * (1.f / DDd);
    float var = redB[32] * (1.f / DDd) - mu * mu;
    float rstd = rsqrtf(var + 1e-5f);
#pragma unroll
    for (int i = 0; i < 4; i++) {
        int d = tid + i * 256;
        out[(size_t)row * DDd + d] = (loc[i] - mu) * rstd * g[d] + b[d];
    }
}

// ---------------- host-side orchestration ----------------
extern "C" void kernel_launch(void* const* d_in, const int* in_sizes, int n_in,
                              void* d_out, int out_size)
{
    const float* x      = (const float*)d_in[0];
    const float* memory = (const float*)d_in[1];
    const float* Wq  = (const float*)d_in[2];
    const float* Wk  = (const float*)d_in[3];
    const float* Wv  = (const float*)d_in[4];
    const float* Wr  = (const float*)d_in[5];
    const float* Wo  = (const float*)d_in[6];
    const float* rwb = (const float*)d_in[7];
    const float* rrb = (const float*)d_in[8];
    const float* ln1g = (const float*)d_in[9];
    const float* ln1b = (const float*)d_in[10];
    const float* ln2g = (const float*)d_in[11];
    const float* ln2b = (const float*)d_in[12];
    const float* W1  = (const float*)d_in[13];
    const float* b1  = (const float*)d_in[14];
    const float* W2  = (const float*)d_in[15];
    const float* b2  = (const float*)d_in[16];
    float* out = (float*)d_out;

    float *pos, *q, *k, *v, *r, *attn, *tmp, *tmp2, *ff, *h, *h1;
    cudaGetSymbolAddress((void**)&pos,  g_pos);
    cudaGetSymbolAddress((void**)&q,    g_q);
    cudaGetSymbolAddress((void**)&k,    g_k);
    cudaGetSymbolAddress((void**)&v,    g_v);
    cudaGetSymbolAddress((void**)&r,    g_r);
    cudaGetSymbolAddress((void**)&attn, g_attn);
    cudaGetSymbolAddress((void**)&tmp,  g_tmp);
    cudaGetSymbolAddress((void**)&tmp2, g_tmp2);
    cudaGetSymbolAddress((void**)&ff,   g_ff);
    cudaGetSymbolAddress((void**)&h,    g_h);
    cudaGetSymbolAddress((void**)&h1,   g_h1);

    cudaFuncSetAttribute(fused_attn, cudaFuncAttributeMaxDynamicSharedMemorySize,
                         SMEM_ATTN_BYTES);

    pos_kernel<<<(TTt * (DDd / 2) + 255) / 256, 256>>>(pos);

    const float* hcur = x;
    for (int l = 0; l < LL; l++) {
        // q/k/v/r grouped: compacted (8, 48) grid, 384 working CTAs
        dim3 gG(DDd / 128, 48);
        grouped_qkvr<<<gG, 256>>>(hcur, memory + (size_t)l * BB * MMm * DDd, pos,
                                  Wq + (size_t)l * DDd * DDd, Wk + (size_t)l * DDd * DDd,
                                  Wv + (size_t)l * DDd * DDd, Wr + (size_t)l * DDd * DDd,
                                  q, k, v, r);

        // flash fused attention (async-pipelined)
        dim3 gA(SSq / SMT, BB * HHh);
        fused_attn<<<gA, 256, SMEM_ATTN_BYTES>>>(
            q, k, v, r, rwb + (size_t)l * HHh * DKk, rrb + (size_t)l * HHh * DKk, attn);

        // output projection: split-K=2, BM=64/BN=128 -> 256 CTAs
        dim3 gO(DDd / 128, (BB * SSq) / 64, 2);
        tc_gemm_splitk<64, 4><<<gO, 256>>>(attn, Wo + (size_t)l * DDd * DDd,
                                           tmp, tmp2, DDd, DDd, nullptr);
        ln_kernel2<<<BB * SSq, 256>>>(tmp, tmp2, hcur,
                                      ln1g + l * DDd, ln1b + l * DDd, h1);

        // FFN
        dim3 gF1(FFf / 128, (BB * SSq) / 128);     // 256 CTAs
        tc_gemm_k<128, 4><<<gF1, 256>>>(h1, W1 + (size_t)l * DDd * FFf, ff,
                                        FFf, DDd, 1.f, b1 + l * FFf, 1);
        // ff2: split-K=2 -> 256 CTAs
        dim3 gF2(DDd / 128, (BB * SSq) / 64, 2);
        tc_gemm_splitk<64, 4><<<gF2, 256>>>(ff, W2 + (size_t)l * FFf * DDd,
                                            tmp, tmp2, DDd, FFf, b2 + l * DDd);

        float* hout = (l == LL - 1) ? out : h;
        ln_kernel2<<<BB * SSq, 256>>>(tmp, tmp2, h1,
                                      ln2g + l * DDd, ln2b + l * DDd, hout);
        hcur = h;
    }
}

// round 9
// speedup vs baseline: 1.5267x; 1.0390x over previous
#include <cuda_runtime.h>
#include <math.h>
#include <stdint.h>

// Problem dims
#define LL  4
#define BB  2
#define SSq 512
#define MMm 512
#define DDd 1024
#define HHh 16
#define DKk 64
#define FFf 4096
#define TTt (SSq + MMm)   // 1024

// ---------------- scratch ----------------
__device__ float g_pos[TTt * DDd];        // tf32 bits
__device__ float g_q  [BB * SSq * DDd];   // fp32 (biases added in fused_attn)
__device__ float g_k  [BB * TTt * DDd];   // tf32 bits
__device__ float g_v  [BB * TTt * DDd];   // tf32 bits
__device__ float g_r  [TTt * DDd];        // tf32 bits
__device__ float g_attn[BB * SSq * DDd];  // tf32 bits
__device__ float g_tmp [BB * SSq * DDd];
__device__ float g_tmp2[BB * SSq * DDd];
__device__ float g_ff  [BB * SSq * FFf];  // tf32 bits
__device__ float g_h   [BB * SSq * DDd];  // fp32 residual
__device__ float g_hc  [BB * SSq * DDd];  // tf32 copy
__device__ float g_h1  [BB * SSq * DDd];  // fp32 residual
__device__ float g_h1c [BB * SSq * DDd];  // tf32 copy
// pre-converted operands (tf32 bits)
__device__ float g_wqc[LL * DDd * DDd];
__device__ float g_wkc[LL * DDd * DDd];
__device__ float g_wvc[LL * DDd * DDd];
__device__ float g_wrc[LL * DDd * DDd];
__device__ float g_woc[LL * DDd * DDd];
__device__ float g_w1c[LL * DDd * FFf];
__device__ float g_w2c[LL * FFf * DDd];
__device__ float g_memc[LL * BB * MMm * DDd];
__device__ float g_xc  [BB * SSq * DDd];

// ---------------- PTX helpers ----------------
__device__ __forceinline__ uint32_t f2tf32(float f) {
    uint32_t u;
    asm("cvt.rna.tf32.f32 %0, %1;" : "=r"(u) : "f"(f));
    return u;
}
__device__ __forceinline__ void mma_tf32(float c[4], const uint32_t a[4], const uint32_t b[2]) {
    asm volatile(
        "mma.sync.aligned.m16n8k8.row.col.f32.tf32.tf32.f32 "
        "{%0,%1,%2,%3},{%4,%5,%6,%7},{%8,%9},{%0,%1,%2,%3};"
        : "+f"(c[0]), "+f"(c[1]), "+f"(c[2]), "+f"(c[3])
        : "r"(a[0]), "r"(a[1]), "r"(a[2]), "r"(a[3]), "r"(b[0]), "r"(b[1]));
}
__device__ __forceinline__ void cp_async16(void* smem, const void* g) {
    uint32_t s = (uint32_t)__cvta_generic_to_shared(smem);
    asm volatile("cp.async.cg.shared.global [%0], [%1], 16;" :: "r"(s), "l"(g));
}
#define CP_COMMIT() asm volatile("cp.async.commit_group;")
#define CP_WAIT(n)  asm volatile("cp.async.wait_group %0;" :: "n"(n))

// ---------------- bulk fp32 -> tf32-bit convert ----------------
__global__ void cvt_tf32_kernel(const float* __restrict__ in, float* __restrict__ out, int n4)
{
    int i = blockIdx.x * 256 + threadIdx.x;
    if (i >= n4) return;
    float4 v = ((const float4*)in)[i];
    uint4 u = make_uint4(f2tf32(v.x), f2tf32(v.y), f2tf32(v.z), f2tf32(v.w));
    ((uint4*)out)[i] = u;
}

// ---------------- positional encodings (tf32 out) ----------------
__global__ void pos_kernel(float* __restrict__ pos)
{
    int idx = blockIdx.x * blockDim.x + threadIdx.x;
    if (idx >= TTt * (DDd / 2)) return;
    int t = idx / (DDd / 2), j = idx % (DDd / 2);
    double invf = exp(((double)(-2 * j) / (double)DDd) * 9.210340371976184);
    double ang  = (double)(TTt - 1 - t) * invf;
    double kk   = floor(ang * 0.15915494309189535);
    float a = (float)(ang - kk * 6.283185307179586);
    pos[(size_t)t * DDd + j]           = __uint_as_float(f2tf32(sinf(a)));
    pos[(size_t)t * DDd + j + DDd / 2] = __uint_as_float(f2tf32(cosf(a)));
}

// ======================================================================
// Async GEMM core: operands are PRE-CONVERTED tf32 bits. Pure
// cp.async -> LDS -> HMMA. Cg = alpha*Ag@Bg (+bias)(+relu)(tf32 out opt).
// ======================================================================
template<int BM, int NWN>
__device__ __forceinline__ void gemm_core_async(
    const float* __restrict__ Ag, const float* __restrict__ Bg, float* __restrict__ Cg,
    int N, int K, int lda, float alpha, const float* __restrict__ biasg, int relu,
    int cvt_out)
{
    constexpr int BN = NWN * 32;
    constexpr int NWM = 8 / NWN;
    constexpr int WM = BM / NWM;
    constexpr int MT = WM / 16;
    constexpr int BPITCH = BN + 8;
    constexpr int NA_CH = BM / 64;
    constexpr int NB_CH = BN / 64;

    __shared__ uint32_t As[2][BM][20];
    __shared__ uint32_t Bs[2][16][BPITCH];

    int tid = threadIdx.x, lane = tid & 31, warp = tid >> 5;
    int g = lane >> 2, tg = lane & 3;
    int warp_m = warp % NWM, warp_n = warp / NWM;
    int wm = warp_m * WM, wn = warp_n * 32;

    float acc[MT][4][4];
#pragma unroll
    for (int mt = 0; mt < MT; mt++)
#pragma unroll
        for (int nt = 0; nt < 4; nt++)
#pragma unroll
            for (int i = 0; i < 4; i++) acc[mt][nt][i] = 0.f;

    int ar[NA_CH], ak[NA_CH];
#pragma unroll
    for (int j = 0; j < NA_CH; j++) {
        int c = tid + j * 256;
        ar[j] = c >> 2; ak[j] = (c & 3) * 4;
    }
    int bk[NB_CH], bn[NB_CH];
#pragma unroll
    for (int j = 0; j < NB_CH; j++) {
        int c = tid + j * 256;
        if (BN == 128) { bk[j] = c >> 5; bn[j] = (c & 31) * 4; }
        else           { bk[j] = c >> 4; bn[j] = (c & 15) * 4; }
    }

    int nk = K / 16;

    // prologue: tile 0
#pragma unroll
    for (int j = 0; j < NA_CH; j++)
        cp_async16(&As[0][ar[j]][ak[j]], Ag + (size_t)ar[j] * lda + ak[j]);
#pragma unroll
    for (int j = 0; j < NB_CH; j++)
        cp_async16(&Bs[0][bk[j]][bn[j]], Bg + (size_t)bk[j] * N + bn[j]);
    CP_COMMIT();

    for (int kt = 0; kt < nk; kt++) {
        int buf = kt & 1;
        bool more = (kt + 1 < nk);
        if (more) {
            int nb = buf ^ 1;
#pragma unroll
            for (int j = 0; j < NA_CH; j++)
                cp_async16(&As[nb][ar[j]][ak[j]],
                           Ag + (size_t)ar[j] * lda + (kt + 1) * 16 + ak[j]);
#pragma unroll
            for (int j = 0; j < NB_CH; j++)
                cp_async16(&Bs[nb][bk[j]][bn[j]],
                           Bg + (size_t)((kt + 1) * 16 + bk[j]) * N + bn[j]);
            CP_COMMIT();
            CP_WAIT(1);
        } else {
            CP_WAIT(0);
        }
        __syncthreads();

#pragma unroll
        for (int ks = 0; ks < 2; ks++) {
            uint32_t af[MT][4], bf[4][2];
#pragma unroll
            for (int mt = 0; mt < MT; mt++) {
                int row = wm + mt * 16;
                af[mt][0] = As[buf][row + g][ks * 8 + tg];
                af[mt][1] = As[buf][row + g + 8][ks * 8 + tg];
                af[mt][2] = As[buf][row + g][ks * 8 + tg + 4];
                af[mt][3] = As[buf][row + g + 8][ks * 8 + tg + 4];
            }
#pragma unroll
            for (int nt = 0; nt < 4; nt++) {
                int col = wn + nt * 8 + g;
                bf[nt][0] = Bs[buf][ks * 8 + tg][col];
                bf[nt][1] = Bs[buf][ks * 8 + tg + 4][col];
            }
#pragma unroll
            for (int mt = 0; mt < MT; mt++)
#pragma unroll
                for (int nt = 0; nt < 4; nt++) mma_tf32(acc[mt][nt], af[mt], bf[nt]);
        }
        if (more) __syncthreads();   // protect next iteration's buffer overwrite
    }

#pragma unroll
    for (int mt = 0; mt < MT; mt++) {
#pragma unroll
        for (int nt = 0; nt < 4; nt++) {
            int row = wm + mt * 16 + g;
            int col = wn + nt * 8 + tg * 2;
            float bx0 = 0.f, bx1 = 0.f;
            if (biasg) { bx0 = biasg[col]; bx1 = biasg[col + 1]; }
            float v0 = acc[mt][nt][0] * alpha + bx0;
            float v1 = acc[mt][nt][1] * alpha + bx1;
            float v2 = acc[mt][nt][2] * alpha + bx0;
            float v3 = acc[mt][nt][3] * alpha + bx1;
            if (relu) {
                v0 = fmaxf(v0, 0.f); v1 = fmaxf(v1, 0.f);
                v2 = fmaxf(v2, 0.f); v3 = fmaxf(v3, 0.f);
            }
            if (cvt_out) {
                v0 = __uint_as_float(f2tf32(v0));
                v1 = __uint_as_float(f2tf32(v1));
                v2 = __uint_as_float(f2tf32(v2));
                v3 = __uint_as_float(f2tf32(v3));
            }
            *(float2*)(Cg + (size_t)row * N + col)       = make_float2(v0, v1);
            *(float2*)(Cg + (size_t)(row + 8) * N + col) = make_float2(v2, v3);
        }
    }
}

template<int BM, int NWN>
__global__ void __launch_bounds__(256) tc_gemm_k(
    const float* __restrict__ A, const float* __restrict__ B, float* __restrict__ C,
    int N, int K, float alpha, const float* __restrict__ bias, int relu, int cvt_out)
{
    constexpr int BN = NWN * 32;
    const float* Ag = A + (size_t)blockIdx.y * BM * K;
    const float* Bg = B + (size_t)blockIdx.x * BN;
    float* Cg = C + (size_t)blockIdx.y * BM * N + (size_t)blockIdx.x * BN;
    const float* bg = bias ? bias + (size_t)blockIdx.x * BN : nullptr;
    gemm_core_async<BM, NWN>(Ag, Bg, Cg, N, K, K, alpha, bg, relu, cvt_out);
}

// split-K=2: z-half writes C0 (z=0) or C1 (z=1); bias only in z=0.
template<int BM, int NWN>
__global__ void __launch_bounds__(256) tc_gemm_splitk(
    const float* __restrict__ A, const float* __restrict__ B,
    float* __restrict__ C0, float* __restrict__ C1,
    int N, int K, const float* __restrict__ bias)
{
    constexpr int BN = NWN * 32;
    int z = blockIdx.z;
    int K2 = K >> 1;
    const float* Ag = A + (size_t)blockIdx.y * BM * K + (size_t)z * K2;
    const float* Bg = B + (size_t)z * K2 * N + (size_t)blockIdx.x * BN;
    float* C = z ? C1 : C0;
    float* Cg = C + (size_t)blockIdx.y * BM * N + (size_t)blockIdx.x * BN;
    const float* bg = (bias && z == 0) ? bias + (size_t)blockIdx.x * BN : nullptr;
    gemm_core_async<BM, NWN>(Ag, Bg, Cg, N, K2, K, 1.f, bg, 0, 0);
}

// grouped q/k/v/r projections. Compacted grid (8, 48): y<8 q, [8,24) k,
// [24,40) v, [40,48) r. All operands pre-converted tf32.
__global__ void __launch_bounds__(256) grouped_qkvr(
    const float* __restrict__ hcc, const float* __restrict__ memc, const float* __restrict__ pos,
    const float* __restrict__ Wq, const float* __restrict__ Wk,
    const float* __restrict__ Wv, const float* __restrict__ Wr,
    float* __restrict__ q, float* __restrict__ k, float* __restrict__ v, float* __restrict__ r)
{
    int y = blockIdx.y;
    const float* Ag; const float* B; float* C; float alpha = 1.f; int cvt = 1;
    if (y < 8) {
        Ag = hcc + (size_t)y * 128 * DDd; B = Wq; C = q + (size_t)y * 128 * DDd;
        alpha = 0.125f; cvt = 0;   // q stays fp32 (bias-add in fused_attn)
    } else if (y < 40) {
        int yy = (y < 24) ? y - 8 : y - 24;
        int row0 = yy * 128;
        int b = row0 >> 10, t0 = row0 & 1023;
        Ag = (t0 < MMm) ? memc + ((size_t)b * MMm + t0) * DDd
                        : hcc  + ((size_t)b * SSq + (t0 - MMm)) * DDd;
        if (y < 24) { B = Wk; C = k + (size_t)yy * 128 * DDd; }
        else        { B = Wv; C = v + (size_t)yy * 128 * DDd; }
    } else {
        int yy = y - 40;
        Ag = pos + (size_t)yy * 128 * DDd; B = Wr; C = r + (size_t)yy * 128 * DDd;
    }
    const float* Bg = B + (size_t)blockIdx.x * 128;
    float* Cg = C + (size_t)blockIdx.x * 128;
    gemm_core_async<128, 4>(Ag, Bg, Cg, DDd, DDd, DDd, alpha, nullptr, 0, cvt);
}

// ======================================================================
// Flash fused attention (R8 verified) + tf32 output store.
// ======================================================================
#define SMT   32
#define TN    64
#define QPITCH 68
#define WPITCH 100
#define SMEM_ATTN_FLOATS (2*SMT*QPITCH + 64*QPITCH + 96*QPITCH + 64*QPITCH + SMT*WPITCH + SMT*QPITCH + 128 + 128 + 32 + 32)
#define SMEM_ATTN_BYTES  (SMEM_ATTN_FLOATS * 4)

__global__ void __launch_bounds__(256) fused_attn(
    const float* __restrict__ q, const float* __restrict__ k, const float* __restrict__ v,
    const float* __restrict__ r, const float* __restrict__ rwb, const float* __restrict__ rrb,
    float* __restrict__ attn)
{
    extern __shared__ float sm[];
    uint32_t* Qcb  = (uint32_t*)sm;
    uint32_t* Qrb  = Qcb + SMT * QPITCH;
    uint32_t* Ktb  = Qrb + SMT * QPITCH;
    uint32_t* Rwb  = Ktb + 64 * QPITCH;
    uint32_t* Vtb  = Rwb + 96 * QPITCH;
    float* QRW     = (float*)(Vtb + 64 * QPITCH);
    uint32_t* Pt   = (uint32_t*)(QRW + SMT * WPITCH);
    float* partm   = (float*)(Pt + SMT * QPITCH);
    float* parts   = partm + 128;
    float* rowm    = parts + 128;
    float* rowsum  = rowm + 32;

    int tid = threadIdx.x, lane = tid & 31, warp = tid >> 5;
    int g = lane >> 2, tg = lane & 3;
    int s0 = (15 - blockIdx.x) * SMT;
    int b = blockIdx.y >> 4, h = blockIdx.y & 15;

    const float* qb = q + (size_t)b * SSq * DDd + h * DKk;
    const float* kb = k + (size_t)b * TTt * DDd + h * DKk;
    const float* vb = v + (size_t)b * TTt * DDd + h * DKk;
    const float* rb = r + h * DKk;
    const float* wbv = rwb + h * DKk;
    const float* rbv = rrb + h * DKk;

    int ntiles = (s0 + 543) / 64 + 1;
    int lrow = tid >> 4, lk0 = (tid & 15) * 4;

    auto issue_KR = [&](int it) {
        if (it < ntiles) {
            int t0 = it * TN, jb = t0 - s0 + 480;
#pragma unroll
            for (int j = 0; j < 4; j++) {
                int row = lrow + j * 16;
                cp_async16(&Ktb[row * QPITCH + lk0], kb + (size_t)(t0 + row) * DDd + lk0);
            }
#pragma unroll
            for (int j = 0; j < 6; j++) {
                int row = lrow + j * 16;
                int jg = jb + row; if (jg > TTt - 1) jg = TTt - 1;
                cp_async16(&Rwb[row * QPITCH + lk0], rb + (size_t)jg * DDd + lk0);
            }
        }
        CP_COMMIT();
    };
    auto issue_V = [&](int it) {
        if (it < ntiles) {
            int t0 = it * TN;
#pragma unroll
            for (int j = 0; j < 4; j++) {
                int row = lrow + j * 16;
                cp_async16(&Vtb[row * QPITCH + lk0], vb + (size_t)(t0 + row) * DDd + lk0);
            }
        }
        CP_COMMIT();
    };

    issue_KR(0);
    issue_V(0);

#pragma unroll
    for (int j = 0; j < 2; j++) {
        int c = tid + j * 256;
        int row = c >> 4, k0 = (c & 15) * 4;
        float4 qv = *(const float4*)(qb + (size_t)(s0 + row) * DDd + k0);
        float4 w4 = *(const float4*)(wbv + k0);
        float4 r4 = *(const float4*)(rbv + k0);
        Qcb[row * QPITCH + k0 + 0] = f2tf32(qv.x + w4.x);
        Qcb[row * QPITCH + k0 + 1] = f2tf32(qv.y + w4.y);
        Qcb[row * QPITCH + k0 + 2] = f2tf32(qv.z + w4.z);
        Qcb[row * QPITCH + k0 + 3] = f2tf32(qv.w + w4.w);
        Qrb[row * QPITCH + k0 + 0] = f2tf32(qv.x + r4.x);
        Qrb[row * QPITCH + k0 + 1] = f2tf32(qv.y + r4.y);
        Qrb[row * QPITCH + k0 + 2] = f2tf32(qv.z + r4.z);
        Qrb[row * QPITCH + k0 + 3] = f2tf32(qv.w + r4.w);
    }
    if (tid < 32) { rowm[tid] = -1e30f; rowsum[tid] = 0.f; }

    int wm2 = (warp & 1) * 16;
    int wn2 = (warp >> 1) * 16;
    int wn3 = (warp >> 1) * 24;
    int wi  = warp >> 1;
    int r1 = wm2 + g, r2 = r1 + 8;

    float oacc[2][4];
#pragma unroll
    for (int nt = 0; nt < 2; nt++)
#pragma unroll
        for (int i = 0; i < 4; i++) oacc[nt][i] = 0.f;

    for (int it = 0; it < ntiles; it++) {
        int t0 = it * TN;
        CP_WAIT(1);
        __syncthreads();

        float ca[2][4], ra[3][4];
#pragma unroll
        for (int nt = 0; nt < 2; nt++)
#pragma unroll
            for (int i = 0; i < 4; i++) ca[nt][i] = 0.f;
#pragma unroll
        for (int nt = 0; nt < 3; nt++)
#pragma unroll
            for (int i = 0; i < 4; i++) ra[nt][i] = 0.f;

#pragma unroll
        for (int k8 = 0; k8 < 64; k8 += 8) {
            uint32_t af[4], afr[4];
            af[0]  = Qcb[(wm2 + g) * QPITCH + k8 + tg];
            af[1]  = Qcb[(wm2 + g + 8) * QPITCH + k8 + tg];
            af[2]  = Qcb[(wm2 + g) * QPITCH + k8 + tg + 4];
            af[3]  = Qcb[(wm2 + g + 8) * QPITCH + k8 + tg + 4];
            afr[0] = Qrb[(wm2 + g) * QPITCH + k8 + tg];
            afr[1] = Qrb[(wm2 + g + 8) * QPITCH + k8 + tg];
            afr[2] = Qrb[(wm2 + g) * QPITCH + k8 + tg + 4];
            afr[3] = Qrb[(wm2 + g + 8) * QPITCH + k8 + tg + 4];
#pragma unroll
            for (int nt = 0; nt < 2; nt++) {
                uint32_t bf[2];
                int col = wn2 + nt * 8 + g;
                bf[0] = Ktb[col * QPITCH + k8 + tg];
                bf[1] = Ktb[col * QPITCH + k8 + tg + 4];
                mma_tf32(ca[nt], af, bf);
            }
#pragma unroll
            for (int nt = 0; nt < 3; nt++) {
                uint32_t bf[2];
                int col = wn3 + nt * 8 + g;
                bf[0] = Rwb[col * QPITCH + k8 + tg];
                bf[1] = Rwb[col * QPITCH + k8 + tg + 4];
                mma_tf32(ra[nt], afr, bf);
            }
        }
#pragma unroll
        for (int nt = 0; nt < 3; nt++) {
            int c0 = wn3 + nt * 8 + tg * 2;
            QRW[r1 * WPITCH + c0]     = ra[nt][0];
            QRW[r1 * WPITCH + c0 + 1] = ra[nt][1];
            QRW[r2 * WPITCH + c0]     = ra[nt][2];
            QRW[r2 * WPITCH + c0 + 1] = ra[nt][3];
        }
        __syncthreads();

        issue_KR(it + 1);

        float l[2][4];
#pragma unroll
        for (int nt = 0; nt < 2; nt++) {
            int tts = wn2 + nt * 8 + tg * 2;
#pragma unroll
            for (int i = 0; i < 4; i++) {
                int si = wm2 + g + ((i >= 2) ? 8 : 0);
                int tt = tts + (i & 1);
                int t = t0 + tt, s = s0 + si;
                l[nt][i] = (t - s <= MMm)
                    ? ca[nt][i] + QRW[si * WPITCH + tt + (SMT - 1) - si]
                    : -1e30f;
            }
        }
        float mx1 = fmaxf(fmaxf(l[0][0], l[0][1]), fmaxf(l[1][0], l[1][1]));
        float mx2 = fmaxf(fmaxf(l[0][2], l[0][3]), fmaxf(l[1][2], l[1][3]));
        mx1 = fmaxf(mx1, __shfl_xor_sync(0xffffffffu, mx1, 1));
        mx1 = fmaxf(mx1, __shfl_xor_sync(0xffffffffu, mx1, 2));
        mx2 = fmaxf(mx2, __shfl_xor_sync(0xffffffffu, mx2, 1));
        mx2 = fmaxf(mx2, __shfl_xor_sync(0xffffffffu, mx2, 2));
        if (tg == 0) { partm[r1 * 4 + wi] = mx1; partm[r2 * 4 + wi] = mx2; }

        CP_WAIT(1);
        __syncthreads();

        float tm1 = fmaxf(fmaxf(partm[r1 * 4 + 0], partm[r1 * 4 + 1]),
                          fmaxf(partm[r1 * 4 + 2], partm[r1 * 4 + 3]));
        float tm2 = fmaxf(fmaxf(partm[r2 * 4 + 0], partm[r2 * 4 + 1]),
                          fmaxf(partm[r2 * 4 + 2], partm[r2 * 4 + 3]));
        float m1 = fmaxf(rowm[r1], tm1);
        float m2 = fmaxf(rowm[r2], tm2);
        float c1 = __expf(rowm[r1] - m1);
        float c2 = __expf(rowm[r2] - m2);
        float s1a = 0.f, s2a = 0.f;
#pragma unroll
        for (int nt = 0; nt < 2; nt++) {
            int tts = wn2 + nt * 8 + tg * 2;
            float p0 = __expf(l[nt][0] - m1);
            float p1 = __expf(l[nt][1] - m1);
            float p2 = __expf(l[nt][2] - m2);
            float p3 = __expf(l[nt][3] - m2);
            Pt[r1 * QPITCH + tts]     = f2tf32(p0);
            Pt[r1 * QPITCH + tts + 1] = f2tf32(p1);
            Pt[r2 * QPITCH + tts]     = f2tf32(p2);
            Pt[r2 * QPITCH + tts + 1] = f2tf32(p3);
            s1a += p0 + p1;
            s2a += p2 + p3;
        }
        s1a += __shfl_xor_sync(0xffffffffu, s1a, 1);
        s1a += __shfl_xor_sync(0xffffffffu, s1a, 2);
        s2a += __shfl_xor_sync(0xffffffffu, s2a, 1);
        s2a += __shfl_xor_sync(0xffffffffu, s2a, 2);
        if (tg == 0) { parts[r1 * 4 + wi] = s1a; parts[r2 * 4 + wi] = s2a; }
#pragma unroll
        for (int nt = 0; nt < 2; nt++) {
            oacc[nt][0] *= c1; oacc[nt][1] *= c1;
            oacc[nt][2] *= c2; oacc[nt][3] *= c2;
        }
        __syncthreads();

        if (wi == 0 && tg == 0) {
            rowsum[r1] = rowsum[r1] * c1 +
                parts[r1 * 4 + 0] + parts[r1 * 4 + 1] + parts[r1 * 4 + 2] + parts[r1 * 4 + 3];
            rowm[r1] = m1;
            rowsum[r2] = rowsum[r2] * c2 +
                parts[r2 * 4 + 0] + parts[r2 * 4 + 1] + parts[r2 * 4 + 2] + parts[r2 * 4 + 3];
            rowm[r2] = m2;
        }

#pragma unroll
        for (int k8 = 0; k8 < 64; k8 += 8) {
            uint32_t af[4];
            af[0] = Pt[r1 * QPITCH + k8 + tg];
            af[1] = Pt[r2 * QPITCH + k8 + tg];
            af[2] = Pt[r1 * QPITCH + k8 + tg + 4];
            af[3] = Pt[r2 * QPITCH + k8 + tg + 4];
#pragma unroll
            for (int nt = 0; nt < 2; nt++) {
                uint32_t bf[2];
                int col = wn2 + nt * 8 + g;
                bf[0] = Vtb[(k8 + tg) * QPITCH + col];
                bf[1] = Vtb[(k8 + tg + 4) * QPITCH + col];
                mma_tf32(oacc[nt], af, bf);
            }
        }
        __syncthreads();
        issue_V(it + 1);
    }

    __syncthreads();
    float inv1 = 1.f / rowsum[r1];
    float inv2 = 1.f / rowsum[r2];
    float* ob = attn + ((size_t)b * SSq + s0) * DDd + h * DKk;
#pragma unroll
    for (int nt = 0; nt < 2; nt++) {
        int c0 = wn2 + nt * 8 + tg * 2;
        *(float2*)(ob + (size_t)r1 * DDd + c0) = make_float2(
            __uint_as_float(f2tf32(oacc[nt][0] * inv1)),
            __uint_as_float(f2tf32(oacc[nt][1] * inv1)));
        *(float2*)(ob + (size_t)r2 * DDd + c0) = make_float2(
            __uint_as_float(f2tf32(oacc[nt][2] * inv2)),
            __uint_as_float(f2tf32(oacc[nt][3] * inv2)));
    }
}

// ---------------- residual + LayerNorm over (x0 + x1 + res), dual output ----------------
__global__ void ln_kernel2(const float* __restrict__ x0, const float* __restrict__ x1,
                           const float* __restrict__ res,
                           const float* __restrict__ g, const float* __restrict__ b,
                           float* __restrict__ out, float* __restrict__ outc)
{
    int row = blockIdx.x;
    const float* xr0 = x0 + (size_t)row * DDd;
    const float* xr1 = x1 + (size_t)row * DDd;
    const float* rr  = res + (size_t)row * DDd;
    __shared__ float redA[33], redB[33];
    int tid = threadIdx.x;

    float loc[4];
    float s1 = 0.f, s2 = 0.f;
#pragma unroll
    for (int i = 0; i < 4; i++) {
        int d = tid + i * 256;
        float v = xr0[d] + xr1[d] + rr[d];
        loc[i] = v;
        s1 += v;
        s2 += v * v;
    }
#pragma unroll
    for (int o = 16; o; o >>= 1) {
        s1 += __shfl_xor_sync(0xffffffffu, s1, o);
        s2 += __shfl_xor_sync(0xffffffffu, s2, o);
    }
    if ((tid & 31) == 0) { redA[tid >> 5] = s1; redB[tid >> 5] = s2; }
    __syncthreads();
    if (tid < 32) {
        float a = (tid < 8) ? redA[tid] : 0.f;
        float c = (tid < 8) ? redB[tid] : 0.f;
#pragma unroll
        for (int o = 4; o; o >>= 1) {
            a += __shfl_xor_sync(0xffffffffu, a, o);
            c += __shfl_xor_sync(0xffffffffu, c, o);
        }
        if (tid == 0) { redA[32] = a; redB[32] = c; }
    }
    __syncthreads();
    float mu  = redA[32] * (1.f / DDd);
    float var = redB[32] * (1.f / DDd) - mu * mu;
    float rstd = rsqrtf(var + 1e-5f);
#pragma unroll
    for (int i = 0; i < 4; i++) {
        int d = tid + i * 256;
        float o = (loc[i] - mu) * rstd * g[d] + b[d];
        out[(size_t)row * DDd + d] = o;
        if (outc) outc[(size_t)row * DDd + d] = __uint_as_float(f2tf32(o));
    }
}

// ---------------- host-side orchestration ----------------
extern "C" void kernel_launch(void* const* d_in, const int* in_sizes, int n_in,
                              void* d_out, int out_size)
{
    const float* x      = (const float*)d_in[0];
    const float* memory = (const float*)d_in[1];
    const float* Wq  = (const float*)d_in[2];
    const float* Wk  = (const float*)d_in[3];
    const float* Wv  = (const float*)d_in[4];
    const float* Wr  = (const float*)d_in[5];
    const float* Wo  = (const float*)d_in[6];
    const float* rwb = (const float*)d_in[7];
    const float* rrb = (const float*)d_in[8];
    const float* ln1g = (const float*)d_in[9];
    const float* ln1b = (const float*)d_in[10];
    const float* ln2g = (const float*)d_in[11];
    const float* ln2b = (const float*)d_in[12];
    const float* W1  = (const float*)d_in[13];
    const float* b1  = (const float*)d_in[14];
    const float* W2  = (const float*)d_in[15];
    const float* b2  = (const float*)d_in[16];
    float* out = (float*)d_out;

    float *pos, *q, *k, *v, *r, *attn, *tmp, *tmp2, *ff, *h, *hc, *h1, *h1c;
    float *wqc, *wkc, *wvc, *wrc, *woc, *w1c, *w2c, *memc, *xc;
    cudaGetSymbolAddress((void**)&pos,  g_pos);
    cudaGetSymbolAddress((void**)&q,    g_q);
    cudaGetSymbolAddress((void**)&k,    g_k);
    cudaGetSymbolAddress((void**)&v,    g_v);
    cudaGetSymbolAddress((void**)&r,    g_r);
    cudaGetSymbolAddress((void**)&attn, g_attn);
    cudaGetSymbolAddress((void**)&tmp,  g_tmp);
    cudaGetSymbolAddress((void**)&tmp2, g_tmp2);
    cudaGetSymbolAddress((void**)&ff,   g_ff);
    cudaGetSymbolAddress((void**)&h,    g_h);
    cudaGetSymbolAddress((void**)&hc,   g_hc);
    cudaGetSymbolAddress((void**)&h1,   g_h1);
    cudaGetSymbolAddress((void**)&h1c,  g_h1c);
    cudaGetSymbolAddress((void**)&wqc,  g_wqc);
    cudaGetSymbolAddress((void**)&wkc,  g_wkc);
    cudaGetSymbolAddress((void**)&wvc,  g_wvc);
    cudaGetSymbolAddress((void**)&wrc,  g_wrc);
    cudaGetSymbolAddress((void**)&woc,  g_woc);
    cudaGetSymbolAddress((void**)&w1c,  g_w1c);
    cudaGetSymbolAddress((void**)&w2c,  g_w2c);
    cudaGetSymbolAddress((void**)&memc, g_memc);
    cudaGetSymbolAddress((void**)&xc,   g_xc);

    cudaFuncSetAttribute(fused_attn, cudaFuncAttributeMaxDynamicSharedMemorySize,
                         SMEM_ATTN_BYTES);

    // one-shot converts (whole multi-layer tensors)
    auto cvt = [&](const float* in, float* o, size_t n) {
        int n4 = (int)(n / 4);
        cvt_tf32_kernel<<<(n4 + 255) / 256, 256>>>(in, o, n4);
    };
    cvt(Wq, wqc, (size_t)LL * DDd * DDd);
    cvt(Wk, wkc, (size_t)LL * DDd * DDd);
    cvt(Wv, wvc, (size_t)LL * DDd * DDd);
    cvt(Wr, wrc, (size_t)LL * DDd * DDd);
    cvt(Wo, woc, (size_t)LL * DDd * DDd);
    cvt(W1, w1c, (size_t)LL * DDd * FFf);
    cvt(W2, w2c, (size_t)LL * FFf * DDd);
    cvt(memory, memc, (size_t)LL * BB * MMm * DDd);
    cvt(x, xc, (size_t)BB * SSq * DDd);

    pos_kernel<<<(TTt * (DDd / 2) + 255) / 256, 256>>>(pos);

    const float* hcur  = x;    // fp32 residual stream
    const float* hcurc = xc;   // tf32 GEMM-A stream
    for (int l = 0; l < LL; l++) {
        dim3 gG(DDd / 128, 48);
        grouped_qkvr<<<gG, 256>>>(hcurc, memc + (size_t)l * BB * MMm * DDd, pos,
                                  wqc + (size_t)l * DDd * DDd, wkc + (size_t)l * DDd * DDd,
                                  wvc + (size_t)l * DDd * DDd, wrc + (size_t)l * DDd * DDd,
                                  q, k, v, r);

        dim3 gA(SSq / SMT, BB * HHh);
        fused_attn<<<gA, 256, SMEM_ATTN_BYTES>>>(
            q, k, v, r, rwb + (size_t)l * HHh * DKk, rrb + (size_t)l * HHh * DKk, attn);

        // output projection: split-K=2
        dim3 gO(DDd / 128, (BB * SSq) / 64, 2);
        tc_gemm_splitk<64, 4><<<gO, 256>>>(attn, woc + (size_t)l * DDd * DDd,
                                           tmp, tmp2, DDd, DDd, nullptr);
        ln_kernel2<<<BB * SSq, 256>>>(tmp, tmp2, hcur,
                                      ln1g + l * DDd, ln1b + l * DDd, h1, h1c);

        // FFN
        dim3 gF1(FFf / 128, (BB * SSq) / 128);
        tc_gemm_k<128, 4><<<gF1, 256>>>(h1c, w1c + (size_t)l * DDd * FFf, ff,
                                        FFf, DDd, 1.f, b1 + l * FFf, 1, 1);
        dim3 gF2(DDd / 128, (BB * SSq) / 64, 2);
        tc_gemm_splitk<64, 4><<<gF2, 256>>>(ff, w2c + (size_t)l * FFf * DDd,
                                            tmp, tmp2, DDd, FFf, b2 + l * DDd);

        if (l == LL - 1) {
            ln_kernel2<<<BB * SSq, 256>>>(tmp, tmp2, h1,
                                          ln2g + l * DDd, ln2b + l * DDd, out, nullptr);
        } else {
            ln_kernel2<<<BB * SSq, 256>>>(tmp, tmp2, h1,
                                          ln2g + l * DDd, ln2b + l * DDd, h, hc);
            hcur = h;
            hcurc = hc;
        }
    }
}